// round 13
// baseline (speedup 1.0000x reference)
#include <cuda_runtime.h>
#include <math.h>

#define PI_D 3.14159265358979323846
typedef unsigned long long ull;

// ----------------------------- scratch (device globals) -----------------------------
__device__ __align__(16) float2 g_S [32*200*400];   // row-FFT'd field, compact rows
__device__ __align__(16) float2 g_S2[32*200*400];   // after col FFT * trans * IFFT
__device__ float2 g_HT[3*400*400];    // transposed transfer functions [m][k][r], pre-scaled 1/400
__device__ float2 g_PH[4*200*200];    // precomputed layer phasors [l][i][j], pre-scaled 1/400
__device__ float  g_Pp[32*200*25];    // horizontal 8-sums of intensity [b][i][j8]
__device__ float  g_pool[625*32];     // pooled [p][b]
__device__ float  g_W1T[625*512];     // W1 transposed [p][hh]
__device__ float  g_R1[512];          // row sums of W1
__device__ float2 g_w400[400];        // e^{-2*pi*i*k/400}, fp64-initialized

// ----------------------------- packed f32x2 helpers (sm_100+) -----------------------
__device__ __forceinline__ ull F2U(float2 v){
    ull r; asm("mov.b64 %0, {%1,%2};" : "=l"(r) : "f"(v.x), "f"(v.y)); return r;
}
__device__ __forceinline__ float2 U2F(ull v){
    float2 r; asm("mov.b64 {%0,%1}, %2;" : "=f"(r.x), "=f"(r.y) : "l"(v)); return r;
}
__device__ __forceinline__ float2 add2(float2 a, float2 b){
    ull r; asm("add.rn.f32x2 %0, %1, %2;" : "=l"(r) : "l"(F2U(a)), "l"(F2U(b)));
    return U2F(r);
}
__device__ __forceinline__ float2 sub2(float2 a, float2 b){   // a - b == fma(b,-1,a), exact
    const ull N1 = 0xBF800000BF800000ULL;
    ull r; asm("fma.rn.f32x2 %0, %1, %2, %3;" : "=l"(r) : "l"(F2U(b)), "l"(N1), "l"(F2U(a)));
    return U2F(r);
}
__device__ __forceinline__ float2 fma2(ull a, ull b, float2 c){
    ull r; asm("fma.rn.f32x2 %0, %1, %2, %3;" : "=l"(r) : "l"(a), "l"(b), "l"(F2U(c)));
    return U2F(r);
}
__device__ __forceinline__ ull pkxx(float2 a){
    ull r; asm("mov.b64 %0, {%1,%2};" : "=l"(r) : "f"(a.x), "f"(a.x)); return r;
}
__device__ __forceinline__ ull pkny(float2 a){
    ull r; asm("mov.b64 %0, {%1,%2};" : "=l"(r) : "f"(-a.y), "f"(a.y)); return r;
}
__device__ __forceinline__ ull pks(float a){     // (a,a)
    ull r; asm("mov.b64 %0, {%1,%1};" : "=l"(r) : "f"(a)); return r;
}

// ----------------------------- complex helpers -----------------------------
__device__ __forceinline__ float2 cmul(float2 a, float2 b){
    return make_float2(fmaf(a.x,b.x,-a.y*b.y), fmaf(a.x,b.y, a.y*b.x));
}
__device__ __forceinline__ float2 cfma(float2 r, float2 a, float2 w){
    r.x = fmaf(a.x,w.x, fmaf(-a.y,w.y,r.x));
    r.y = fmaf(a.x,w.y, fmaf( a.y,w.x,r.y));
    return r;
}
template<bool INV>
__device__ __forceinline__ float2 TW(int m){   // W400^m (conj if INV)
    float2 v = g_w400[m];
    if (INV) v.y = -v.y;
    return v;
}

// ----------------------------- FFT-20 (registers, packed f32x2): n=20 --------------
// HZ:   inputs a[5..14] are identically zero (never read).
// CROP: only outputs k in {0..4, 15..19} are produced (a[5..14] left garbage).
template<bool INV, bool HZ, bool CROP>
__device__ __forceinline__ void fft20(float2* a){
    float2 t[20];
    #pragma unroll
    for (int j2=0;j2<5;j2++){
        float2 y0,y1,y2,y3;
        if (HZ){
            float2 x0=a[j2], x3=a[15+j2];
            y0 = add2(x0,x3);
            y2 = sub2(x0,x3);
            if (!INV){ y1 = make_float2(x0.x - x3.y, x0.y + x3.x);
                       y3 = make_float2(x0.x + x3.y, x0.y - x3.x); }
            else     { y1 = make_float2(x0.x + x3.y, x0.y - x3.x);
                       y3 = make_float2(x0.x - x3.y, x0.y + x3.x); }
        } else {
            float2 x0=a[j2], x1=a[5+j2], x2=a[10+j2], x3=a[15+j2];
            float2 s02=add2(x0,x2), d02=sub2(x0,x2);
            float2 s13=add2(x1,x3), d13=sub2(x1,x3);
            y0=add2(s02,s13);
            y2=sub2(s02,s13);
            if (!INV){ y1=make_float2(d02.x+d13.y, d02.y-d13.x);
                       y3=make_float2(d02.x-d13.y, d02.y+d13.x); }
            else     { y1=make_float2(d02.x-d13.y, d02.y+d13.x);
                       y3=make_float2(d02.x+d13.y, d02.y-d13.x); }
        }
        t[j2] = y0;
        if (j2 == 0){               // W^0 == (1,0): skip identity multiplies
            t[5]  = y1;
            t[10] = y2;
            t[15] = y3;
        } else {
            t[5+j2]  = cmul(y1, TW<INV>(20*j2));
            t[10+j2] = cmul(y2, TW<INV>(40*j2));
            t[15+j2] = cmul(y3, TW<INV>(60*j2));
        }
    }
    const float C1f= 0.30901699437494742f, S1f=0.95105651629515357f;
    const float C2f=-0.80901699437494745f, S2f=0.58778525229247313f;
    const float si = INV ? 1.f : -1.f;
    const float2 w1=make_float2(C1f, si*S1f), w2=make_float2(C2f, si*S2f);
    const float2 w3=make_float2(C2f,-si*S2f), w4=make_float2(C1f,-si*S1f);
    ull W1p=F2U(w1), W2p=F2U(w2), W3p=F2U(w3), W4p=F2U(w4);
    ull W1s=F2U(make_float2(w1.y,w1.x)), W2s=F2U(make_float2(w2.y,w2.x));
    ull W3s=F2U(make_float2(w3.y,w3.x)), W4s=F2U(make_float2(w4.y,w4.x));
    #pragma unroll
    for (int k1=0;k1<4;k1++){
        float2 b0=t[k1*5], b1=t[k1*5+1], b2=t[k1*5+2], b3=t[k1*5+3], b4=t[k1*5+4];
        a[k1] = add2(add2(add2(add2(b0,b1),b2),b3),b4);
        if (!CROP){
            ull b1x=pkxx(b1), b1n=pkny(b1);
            ull b2x=pkxx(b2), b2n=pkny(b2);
            ull b3x=pkxx(b3), b3n=pkny(b3);
            ull b4x=pkxx(b4), b4n=pkny(b4);
            float2 y1 = fma2(b1x,W1p, fma2(b1n,W1s, b0));
            y1 = fma2(b2x,W2p, fma2(b2n,W2s, y1));
            y1 = fma2(b3x,W3p, fma2(b3n,W3s, y1));
            y1 = fma2(b4x,W4p, fma2(b4n,W4s, y1));
            a[k1+4]=y1;
            float2 y2 = fma2(b1x,W2p, fma2(b1n,W2s, b0));
            y2 = fma2(b2x,W4p, fma2(b2n,W4s, y2));
            y2 = fma2(b3x,W1p, fma2(b3n,W1s, y2));
            y2 = fma2(b4x,W3p, fma2(b4n,W3s, y2));
            a[k1+8]=y2;
            float2 y3 = fma2(b1x,W3p, fma2(b1n,W3s, b0));
            y3 = fma2(b2x,W1p, fma2(b2n,W1s, y3));
            y3 = fma2(b3x,W4p, fma2(b3n,W4s, y3));
            y3 = fma2(b4x,W2p, fma2(b4n,W2s, y3));
            a[k1+12]=y3;
            float2 y4 = fma2(b1x,W4p, fma2(b1n,W4s, b0));
            y4 = fma2(b2x,W3p, fma2(b2n,W3s, y4));
            y4 = fma2(b3x,W2p, fma2(b3n,W2s, y4));
            y4 = fma2(b4x,W1p, fma2(b4n,W1s, y4));
            a[k1+16]=y4;
        } else {
            if (k1==0){
                float2 y1=b0; y1=cfma(y1,b1,w1); y1=cfma(y1,b2,w2); y1=cfma(y1,b3,w3); y1=cfma(y1,b4,w4);
                a[4]=y1;
            }
            if (k1==3){
                float2 y3=b0; y3=cfma(y3,b1,w3); y3=cfma(y3,b2,w1); y3=cfma(y3,b3,w4); y3=cfma(y3,b4,w2);
                a[15]=y3;
            }
            float2 y4=b0; y4=cfma(y4,b1,w4); y4=cfma(y4,b2,w3); y4=cfma(y4,b3,w2); y4=cfma(y4,b4,w1);
            a[k1+16]=y4;
        }
    }
}

// ----------------------------- incremental inter-stage twiddles --------------------
template<bool INV>
__device__ __forceinline__ void twiddle_apply(float2* r, int lane){
    float2 Wa = TW<INV>(lane);
    float2 A5 = TW<INV>(5*lane);
    float2 A10= TW<INV>(10*lane);
    float2 A15= TW<INV>(15*lane);
    float2 W2 = cmul(Wa,Wa);
    float2 W3 = cmul(W2,Wa);
    float2 W4 = cmul(W3,Wa);
    r[1]=cmul(r[1],Wa);  r[2]=cmul(r[2],W2);
    r[3]=cmul(r[3],W3);  r[4]=cmul(r[4],W4);
    r[5]=cmul(r[5],A5);
    r[6]=cmul(r[6],cmul(A5,Wa));   r[7]=cmul(r[7],cmul(A5,W2));
    r[8]=cmul(r[8],cmul(A5,W3));   r[9]=cmul(r[9],cmul(A5,W4));
    r[10]=cmul(r[10],A10);
    r[11]=cmul(r[11],cmul(A10,Wa)); r[12]=cmul(r[12],cmul(A10,W2));
    r[13]=cmul(r[13],cmul(A10,W3)); r[14]=cmul(r[14],cmul(A10,W4));
    r[15]=cmul(r[15],A15);
    r[16]=cmul(r[16],cmul(A15,Wa)); r[17]=cmul(r[17],cmul(A15,W2));
    r[18]=cmul(r[18],cmul(A15,W3)); r[19]=cmul(r[19],cmul(A15,W4));
}

// ----------------------------- FFT-400 (warp, 20 active lanes): 20x20 four-step ----
// (generic version kept for kA0 / kCF)
template<bool INV, bool HZ, bool CROP>
__device__ void fft400(float2* __restrict__ lin, float2* __restrict__ tmp, int lane){
    __syncwarp();
    float2 r[20];
    if (lane < 20){
        if (HZ){
            #pragma unroll
            for (int j1=0;j1<5;j1++)  r[j1]=lin[j1*20+lane];
            #pragma unroll
            for (int j1=15;j1<20;j1++) r[j1]=lin[j1*20+lane];
        } else {
            #pragma unroll
            for (int j1=0;j1<20;j1++) r[j1]=lin[j1*20+lane];
        }
        fft20<INV,HZ,false>(r);
        twiddle_apply<INV>(r,lane);
        #pragma unroll
        for (int k1=0;k1<20;k1++) tmp[k1*21+lane]=r[k1];
    }
    __syncwarp();
    if (lane < 20){
        #pragma unroll
        for (int j2=0;j2<20;j2++) r[j2]=tmp[lane*21+j2];
        fft20<INV,false,CROP>(r);
        #pragma unroll
        for (int k2=0;k2<20;k2++)
            if (!CROP || k2<5 || k2>=15) lin[k2*20+lane]=r[k2];
    }
    __syncwarp();
}

// ----------------------------- kB fused transform: fwd FFT -> *H -> inv FFT --------
__device__ void fftB_fused(float2* __restrict__ col, float2* __restrict__ tmp,
                           int lane, const float2* __restrict__ ht){
    __syncwarp();
    float2 r[20];
    if (lane < 20){
        #pragma unroll
        for (int j1=0;j1<5;j1++)  r[j1]=col[j1*20+lane];
        #pragma unroll
        for (int j1=15;j1<20;j1++) r[j1]=col[j1*20+lane];
        fft20<false,true,false>(r);          // fwd stage1 (half-zero)
        twiddle_apply<false>(r,lane);
        #pragma unroll
        for (int k1=0;k1<20;k1++) tmp[k1*21+lane]=r[k1];
    }
    __syncwarp();
    if (lane < 20){
        #pragma unroll
        for (int j2=0;j2<20;j2++) r[j2]=tmp[lane*21+j2];
    }
    __syncwarp();                            // tmp reads done before overwrite
    if (lane < 20){
        fft20<false,false,false>(r);         // fwd stage2 -> X at pos 20m+lane
        #pragma unroll
        for (int j1=0;j1<20;j1++) r[j1]=cmul(r[j1], ht[j1*20+lane]);  // *H (pre-scaled)
        fft20<true,false,false>(r);          // inv stage1
        twiddle_apply<true>(r,lane);
        #pragma unroll
        for (int k1=0;k1<20;k1++) tmp[k1*21+lane]=r[k1];
    }
    __syncwarp();
    if (lane < 20){
        #pragma unroll
        for (int j2=0;j2<20;j2++) r[j2]=tmp[lane*21+j2];
        fft20<true,false,true>(r);           // inv stage2, cropped
        #pragma unroll
        for (int k2=0;k2<20;k2++)
            if (k2<5 || k2>=15) col[k2*20+lane]=r[k2];
    }
    __syncwarp();
}

// ----------------------------- kC fused transform: inv FFT -> phasor -> fwd FFT ----
__device__ void fftC_fused(float2* __restrict__ lin, float2* __restrict__ tmp,
                           int lane, const float2* __restrict__ ph){
    __syncwarp();
    float2 r[20];
    if (lane < 20){
        #pragma unroll
        for (int j1=0;j1<20;j1++) r[j1]=lin[j1*20+lane];
        fft20<true,false,false>(r);          // inv stage1
        twiddle_apply<true>(r,lane);
        #pragma unroll
        for (int k1=0;k1<20;k1++) tmp[k1*21+lane]=r[k1];
    }
    __syncwarp();
    if (lane < 20){
        #pragma unroll
        for (int j2=0;j2<20;j2++) r[j2]=tmp[lane*21+j2];
    }
    __syncwarp();                            // tmp reads done before overwrite
    if (lane < 20){
        fft20<true,false,true>(r);           // inv stage2 CROP: corners valid
        if (ph){
            #pragma unroll
            for (int k2=0;k2<5;k2++)   r[k2] = cmul(r[k2], ph[20*k2+lane+100]);
            #pragma unroll
            for (int k2=15;k2<20;k2++) r[k2] = cmul(r[k2], ph[20*k2+lane-300]);
        } else {
            const float sc = 1.f/400.f;
            #pragma unroll
            for (int k2=0;k2<5;k2++){  r[k2].x*=sc; r[k2].y*=sc; }
            #pragma unroll
            for (int k2=15;k2<20;k2++){ r[k2].x*=sc; r[k2].y*=sc; }
        }
        fft20<false,true,false>(r);          // fwd stage1 (half-zero corners)
        twiddle_apply<false>(r,lane);
        #pragma unroll
        for (int k1=0;k1<20;k1++) tmp[k1*21+lane]=r[k1];
    }
    __syncwarp();
    if (lane < 20){
        #pragma unroll
        for (int j2=0;j2<20;j2++) r[j2]=tmp[lane*21+j2];
        fft20<false,false,false>(r);         // fwd stage2
        #pragma unroll
        for (int k2=0;k2<20;k2++) lin[k2*20+lane]=r[k2];
    }
    __syncwarp();
}

#define WPB 4  // warps (transforms) per block for row-FFT kernels

// ----------------------------- init: twiddles + zero histogram -----------------------------
__global__ void kInit(float* out){
    int k = threadIdx.x;
    if (k < 400){
        double ang = -2.0*PI_D*(double)k/400.0;
        g_w400[k] = make_float2((float)cos(ang), (float)sin(ang));
    }
    if (k < 11) out[1250+k] = 0.f;
}

// ----------------------------- precompute layer phasors (pre-scaled by 1/400) ------
__global__ void kPrep(const float* __restrict__ phase){
    int idx = blockIdx.x*256 + threadIdx.x;
    if (idx >= 4*40000) return;
    float p = phase[idx];
    float sv, cv;
    sincospif(2.f*(sinf(p)+1.f), &sv, &cv);   // e^{i*2*pi*(sin(p)+1)}
    const float sc = 1.f/400.f;
    g_PH[idx] = make_float2(cv*sc, sv*sc);
}

// ----------------------------- transpose transfer functions (pre-scaled by 1/400) --
__global__ void kHT(const float2* __restrict__ t0, const float2* __restrict__ t1,
                    const float2* __restrict__ t2){
    __shared__ float2 tile[32][33];
    int m = blockIdx.z;
    const float2* src = (m==0)? t0 : (m==1)? t1 : t2;
    int r0 = blockIdx.y*32, k0 = blockIdx.x*32;
    int tx = threadIdx.x, ty = threadIdx.y;   // 32 x 8
    const float sc = 1.f/400.f;
    for (int yy=ty; yy<32; yy+=8){
        int r = r0+yy, k = k0+tx;
        if (r<400 && k<400) tile[yy][tx] = src[r*400+k];
    }
    __syncthreads();
    for (int yy=ty; yy<32; yy+=8){
        int k = k0+yy, r = r0+tx;
        if (r<400 && k<400){
            float2 v = tile[tx][yy];
            g_HT[(size_t)m*160000 + k*400 + r] = make_float2(v.x*sc, v.y*sc);
        }
    }
}

// ----------------------------- W1 transpose (tiled) + row sums -----------------------------
__global__ void kT(const float* __restrict__ W1){
    __shared__ float tile[32][33];
    int p0 = blockIdx.x*32, h0 = blockIdx.y*32;
    int tx = threadIdx.x, ty = threadIdx.y;   // 32 x 8
    for (int yy=ty; yy<32; yy+=8){
        int hh = h0+yy, p = p0+tx;
        if (hh<512 && p<625) tile[yy][tx] = W1[hh*625+p];
    }
    __syncthreads();
    for (int yy=ty; yy<32; yy+=8){
        int p = p0+yy, hh = h0+tx;
        if (p<625 && hh<512) g_W1T[p*512+hh] = tile[tx][yy];
    }
}
__global__ void kR1(const float* __restrict__ W1){   // grid 512, block 128
    __shared__ float red[128];
    int hh = blockIdx.x, tid = threadIdx.x;
    float s = 0.f;
    for (int p=tid; p<625; p+=128) s += W1[hh*625+p];
    red[tid] = s;
    __syncthreads();
    for (int st=64; st>0; st>>=1){
        if (tid<st) red[tid]+=red[tid+st];
        __syncthreads();
    }
    if (tid==0) g_R1[hh] = red[0];
}

// ----------------------------- A0: real input, 2 rows packed per complex FFT --------
__global__ void kA0(const float* __restrict__ x){   // grid 800, block 128
    __shared__ __align__(16) float2 s_lin[WPB][400];
    __shared__ float2 s_tmp[WPB][421];
    int w = threadIdx.x>>5, lane = threadIdx.x&31;
    int idx = blockIdx.x*WPB + w;                   // 0..3199 row-pairs
    int b = idx/100, pr = idx%100;
    int c0 = 2*pr, c1 = 2*pr+1;
    int i0 = (c0<100)? c0+100 : c0-100;             // logical rows
    int i1 = (c1<100)? c1+100 : c1-100;
    const float4* x0r4 = (const float4*)(x + ((size_t)b*200 + i0)*200);
    const float4* x1r4 = (const float4*)(x + ((size_t)b*200 + i1)*200);
    float2* lin = s_lin[w]; float2* tmp = s_tmp[w];
    if (lane < 25){
        float4 a0 = x0r4[25+lane], b0 = x1r4[25+lane];   // x[100..199] -> lin[0..99]
        lin[4*lane  ] = make_float2(a0.x, b0.x);
        lin[4*lane+1] = make_float2(a0.y, b0.y);
        lin[4*lane+2] = make_float2(a0.z, b0.z);
        lin[4*lane+3] = make_float2(a0.w, b0.w);
        float4 a1 = x0r4[lane],    b1 = x1r4[lane];      // x[0..99] -> lin[300..399]
        lin[300+4*lane  ] = make_float2(a1.x, b1.x);
        lin[300+4*lane+1] = make_float2(a1.y, b1.y);
        lin[300+4*lane+2] = make_float2(a1.z, b1.z);
        lin[300+4*lane+3] = make_float2(a1.w, b1.w);
    }
    fft400<false,true,false>(lin,tmp,lane);
    float2* row0 = g_S + ((size_t)b*200+c0)*400;
    float2* row1 = g_S + ((size_t)b*200+c1)*400;
    for (int k=lane; k<400; k+=32){
        float2 Zk = lin[k];
        float2 Zr = lin[(400-k) & 399];   // (400-k)%400; k=0 -> 0
        row0[k] = make_float2(0.5f*(Zk.x+Zr.x),  0.5f*(Zk.y-Zr.y));
        row1[k] = make_float2(0.5f*(Zk.y+Zr.y), -0.5f*(Zk.x-Zr.x));
    }
}

// ----------------------------- B (warp-private): fused col FFT*H*IFFT ---------------
__global__ void __launch_bounds__(128) kB(int hm){
    __shared__ __align__(16) float2 colb[8][401];
    __shared__ float2 tmpb[4][421];
    int b  = blockIdx.x / 50;
    int k0 = (blockIdx.x % 50) * 8;
    int tid = threadIdx.x;
    const float4* Sb4 = (const float4*)(g_S + (size_t)b*200*400);
    const float2* HT = g_HT + (size_t)hm*160000;

    // stage in (float4 = 2 complex): col[kl][r], r in [0,100) U [300,400)
    for (int idx=tid; idx<800; idx+=128){
        int c = idx>>2, q = idx&3;
        float4 v = Sb4[c*200 + (k0>>1) + q];
        int r = (c<100)? c : c+200;
        colb[2*q  ][r] = make_float2(v.x,v.y);
        colb[2*q+1][r] = make_float2(v.z,v.w);
    }
    __syncthreads();

    int w = tid>>5, lane = tid&31;
    fftB_fused(colb[2*w  ], tmpb[w], lane, HT + (size_t)(k0+2*w  )*400);
    fftB_fused(colb[2*w+1], tmpb[w], lane, HT + (size_t)(k0+2*w+1)*400);
    __syncthreads();

    // stage out (float4), crop rows (no scale: folded into HT)
    float4* S2b4 = (float4*)(g_S2 + (size_t)b*200*400);
    for (int idx=tid; idx<800; idx+=128){
        int c = idx>>2, q = idx&3;
        int r = (c<100)? c : c+200;
        float2 v0 = colb[2*q  ][r];
        float2 v1 = colb[2*q+1][r];
        S2b4[c*200 + (k0>>1) + q] = make_float4(v0.x, v0.y, v1.x, v1.y);
    }
}

// ----------------------------- C: fused row IFFT -> phasor -> row FFT ---------------
__global__ void kC(int l){   // l < 0: no phasor (first boundary)
    __shared__ __align__(16) float2 s_lin[WPB][400];
    __shared__ float2 s_tmp[WPB][421];
    int w = threadIdx.x>>5, lane = threadIdx.x&31;
    int idx = blockIdx.x*WPB + w;
    int b = idx/200, c = idx%200;
    float2* lin = s_lin[w]; float2* tmp = s_tmp[w];
    const float4* S4 = (const float4*)(g_S2 + ((size_t)b*200+c)*400);
    float4* lin4 = (float4*)lin;
    for (int m4=lane;m4<200;m4+=32) lin4[m4]=S4[m4];
    int i = (c<100)? c+100 : c-100;                 // logical row
    const float2* phrow = (l>=0)? (g_PH + (size_t)l*40000 + i*200) : nullptr;
    fftC_fused(lin,tmp,lane,phrow);
    float4* out4 = (float4*)(g_S + ((size_t)b*200+c)*400);
    const float4* l4 = (const float4*)lin;
    for (int m4=lane;m4<200;m4+=32) out4[m4]=l4[m4];
}

// ----------------------------- CF: row IFFT -> intensity -> horizontal 8-sums ------
__global__ void kCF(){
    __shared__ __align__(16) float2 s_lin[WPB][400];
    __shared__ float2 s_tmp[WPB][421];
    int w = threadIdx.x>>5, lane = threadIdx.x&31;
    int idx = blockIdx.x*WPB + w;
    int b = idx/200, c = idx%200;
    float2* lin = s_lin[w]; float2* tmp = s_tmp[w];
    const float4* S4 = (const float4*)(g_S2 + ((size_t)b*200+c)*400);
    float4* lin4 = (float4*)lin;
    for (int m4=lane;m4<200;m4+=32) lin4[m4]=S4[m4];
    fft400<true,false,true>(lin,tmp,lane);          // cropped inverse
    int i = (c<100)? c+100 : c-100;
    float* pbuf = (float*)tmp;                      // tmp is free now; 200 floats
    const float sc = 1.f/400.f;
    for (int cc=lane;cc<200;cc+=32){
        int rc = (cc<100)? cc : cc+200;
        int j  = (cc<100)? cc+100 : cc-100;
        float vx = lin[rc].x*sc, vy = lin[rc].y*sc;
        pbuf[j] = vx*vx + vy*vy;
    }
    __syncwarp();
    if (lane < 25){
        float s = 0.f;
        #pragma unroll
        for (int v=0; v<8; v++) s += pbuf[lane*8+v];
        g_Pp[((size_t)b*200+i)*25 + lane] = s;
    }
}

// ----------------------------- pooling: vertical sum of 8 partials -> [p][b] -------
__global__ void kPool(){
    int idx = blockIdx.x*256 + threadIdx.x;
    if (idx >= 20000) return;
    int b = idx / 625, p = idx % 625;
    int mi = p/25, mj = p%25;
    const float* base = g_Pp + ((size_t)b*200 + mi*8)*25 + mj;
    float s = 0.f;
    #pragma unroll
    for (int u=0;u<8;u++) s += base[u*25];
    g_pool[p*32+b] = s*(1.f/64.f);
}

// ----------------------------- per-window MLP + voting -----------------------------
#define HSTR 514    // padded hid stride (even: 8B-aligned float2 loads, conflict-safe)
__global__ void __launch_bounds__(256) kWin(
                     const float* __restrict__ b1, const float* __restrict__ W2,
                     const float* __restrict__ b2, const float* __restrict__ gamma,
                     const float* __restrict__ beta, float* __restrict__ out)
{
    extern __shared__ float dsm[];
    float* swin = dsm;                    // [cell][b] up to 25*32
    float* hid  = dsm + 800;              // [b][hh] 32*HSTR
    float* lg   = dsm + 800 + 32*HSTR;    // [b][o]  32*10
    __shared__ double red1[256], red2[256];
    __shared__ int   pidx[25];
    __shared__ float s_inv, s_c0;
    __shared__ int   s_a[32];
    __shared__ float s_delta[32];

    int wI = blockIdx.x;
    int i = wI/25, j = wI%25;
    int wr = min(5, 25-i), wc = min(5, 25-j);
    int cells = wr*wc;
    int tid = threadIdx.x;
    if (tid < cells) pidx[tid] = (i + tid/wc)*25 + (j + tid%wc);
    __syncthreads();

    double s1 = 0.0, s2 = 0.0;
    for (int q=tid; q<cells*32; q+=256){
        int cell = q>>5, b = q&31;
        float v = g_pool[pidx[cell]*32 + b];
        swin[q] = v;
        s1 += v; s2 += (double)v*(double)v;
    }
    red1[tid]=s1; red2[tid]=s2;
    __syncthreads();
    for (int st=128; st>0; st>>=1){
        if (tid<st){ red1[tid]+=red1[tid+st]; red2[tid]+=red2[tid+st]; }
        __syncthreads();
    }
    if (tid == 0){
        double mu  = red1[0]/20000.0;
        double var = red2[0]/20000.0 - mu*mu;
        float inv = gamma[0]/(float)sqrt(var + 1e-5);
        s_inv = inv;
        s_c0  = beta[0] - (float)mu*inv;
    }
    __syncthreads();
    float inv = s_inv, c0 = s_c0;

    // hid[b][hh] = relu(c0*R1 + inv*<win,W1win> + b1); 8 batches/thread, packed f32x2.
    for (int it=0; it<8; it++){
        int task = it*256 + tid;          // 2048 tasks = 4 bgroups x 512 hh
        int hh = task & 511, bg = task >> 9;
        float2 acc2[4];
        #pragma unroll
        for (int v=0;v<4;v++) acc2[v]=make_float2(0.f,0.f);
        for (int cell=0; cell<cells; cell++){
            ull wvp = pks(g_W1T[pidx[cell]*512+hh]);
            const float2* sw2 = (const float2*)(swin + cell*32 + bg*8);
            #pragma unroll
            for (int v=0;v<4;v++) acc2[v] = fma2(F2U(sw2[v]), wvp, acc2[v]);
        }
        float base = fmaf(c0, g_R1[hh], b1[hh]);
        #pragma unroll
        for (int v=0;v<4;v++){
            hid[(bg*8+2*v  )*HSTR + hh] = fmaxf(fmaf(inv, acc2[v].x, base), 0.f);
            hid[(bg*8+2*v+1)*HSTR + hh] = fmaxf(fmaf(inv, acc2[v].y, base), 0.f);
        }
    }
    __syncthreads();

    for (int t=tid; t<320; t+=256){
        int b = t/10, oo = t%10;
        const float2* hb2 = (const float2*)(hid + b*HSTR);   // HSTR even -> aligned
        const float2* wv2 = (const float2*)(W2 + oo*512);
        float2 acc2 = make_float2(0.f,0.f);
        for (int h2=0; h2<256; h2++)
            acc2 = fma2(F2U(hb2[h2]), F2U(wv2[h2]), acc2);
        lg[b*10+oo] = b2[oo] + acc2.x + acc2.y;
    }
    __syncthreads();

    if (tid < 32){
        int b = tid;
        float lmax = lg[b*10], lmin = lg[b*10];
        int am = 0;
        for (int oo=1;oo<10;oo++){
            float v = lg[b*10+oo];
            if (v > lmax){ lmax = v; am = oo; }
            if (v < lmin)  lmin = v;
        }
        float se = 0.f;
        for (int oo=0;oo<10;oo++) se += expf(lg[b*10+oo]-lmax);
        s_a[b] = am;
        s_delta[b] = (1.f - expf(lmin-lmax))/se;  // pmax - pmin
    }
    __syncthreads();
    if (tid == 0){
        int votes[11];
        for (int k=0;k<11;k++) votes[k]=0;
        for (int b=0;b<32;b++) votes[s_a[b]]++;
        int f0 = 0, best = votes[0];
        for (int k=1;k<11;k++) if (votes[k] > best){ best = votes[k]; f0 = k; }
        float sum = 0.f; int cnt = 0;
        for (int b=0;b<32;b++)
            if (s_a[b]==f0 && s_delta[b]!=0.f){ sum += s_delta[b]; cnt++; }
        int fin;
        if (cnt > 0){ float d1 = sum/(float)cnt; fin = (d1 < 0.2f) ? 0 : f0+1; }
        else fin = f0+1;   // delta1 = NaN; NaN < THR is false
        out[wI]       = (fin==0) ? 0.f : (float)fin;
        out[625+wI]   = (fin!=0) ? 1.f : 0.f;
        atomicAdd(&out[1250+fin], 1.0f);   // exact integer counts -> deterministic
    }
}

// ----------------------------- launch -----------------------------
extern "C" void kernel_launch(void* const* d_in, const int* in_sizes, int n_in,
                              void* d_out, int out_size)
{
    int o = (n_in >= 12 && in_sizes[1] == 1) ? 1 : 0;  // skip batch_size scalar if present
    const float*  x     = (const float*) d_in[0];
    const float2* h     = (const float2*)d_in[1+o];
    const float2* h_pro = (const float2*)d_in[2+o];
    const float2* h_det = (const float2*)d_in[3+o];
    const float*  phase = (const float*) d_in[4+o];
    const float*  W1    = (const float*) d_in[5+o];
    const float*  b1    = (const float*) d_in[6+o];
    const float*  W2    = (const float*) d_in[7+o];
    const float*  b2    = (const float*) d_in[8+o];
    const float*  gamma = (const float*) d_in[9+o];
    const float*  beta  = (const float*) d_in[10+o];
    float* out = (float*)d_out;

    cudaFuncSetAttribute(kWin, cudaFuncAttributeMaxDynamicSharedMemorySize,
                         (800 + 32*HSTR + 320)*4);

    // Order: kB is the 4th launch (ncu's captured slot) for diagnostics.
    kInit<<<1,512>>>(out);
    kHT <<<dim3(13,13,3),dim3(32,8)>>>(h_pro, h, h_det);   // [0]=h_pro, [1]=h, [2]=h_det
    kA0 <<<800,128>>>(x);                  // 2 rows per FFT (real packing)
    kB  <<<1600,128>>>(0);                 // h_pro  <-- profiled slot
    kPrep<<<625,256>>>(phase);
    kT  <<<dim3(20,16),dim3(32,8)>>>(W1);
    kR1 <<<512,128>>>(W1);
    kC  <<<1600,128>>>(-1);
    for (int l=0; l<4; l++){
        kB <<<1600,128>>>(1);              // h (transposed once, reused 4x)
        kC <<<1600,128>>>(l);
    }
    kB  <<<1600,128>>>(2);                 // h_det
    kCF <<<1600,128>>>();

    kPool<<<79,256>>>();

    kWin<<<625,256,(800 + 32*HSTR + 320)*4>>>(b1, W2, b2, gamma, beta, out);
}

// round 14
// speedup vs baseline: 1.0481x; 1.0481x over previous
#include <cuda_runtime.h>
#include <math.h>

#define PI_D 3.14159265358979323846
typedef unsigned long long ull;

// ----------------------------- scratch (device globals) -----------------------------
__device__ __align__(16) float2 g_S [32*200*400];   // row-FFT'd field, compact rows
__device__ __align__(16) float2 g_S2[32*200*400];   // after col FFT * trans * IFFT
__device__ float2 g_HT[3*400*400];    // transposed transfer functions [m][k][r], pre-scaled 1/400
__device__ float2 g_PH[4*200*200];    // precomputed layer phasors [l][i][j], pre-scaled 1/400
__device__ float  g_Pp[32*200*25];    // horizontal 8-sums of intensity [b][i][j8]
__device__ float  g_pool[625*32];     // pooled [p][b]
__device__ float  g_W1T[625*512];     // W1 transposed [p][hh]
__device__ float  g_R1[512];          // row sums of W1
__device__ float2 g_w400[400];        // e^{-2*pi*i*k/400}, fp64-initialized

// ----------------------------- packed f32x2 helpers (sm_100+) -----------------------
__device__ __forceinline__ ull F2U(float2 v){
    ull r; asm("mov.b64 %0, {%1,%2};" : "=l"(r) : "f"(v.x), "f"(v.y)); return r;
}
__device__ __forceinline__ float2 U2F(ull v){
    float2 r; asm("mov.b64 {%0,%1}, %2;" : "=f"(r.x), "=f"(r.y) : "l"(v)); return r;
}
__device__ __forceinline__ float2 add2(float2 a, float2 b){
    ull r; asm("add.rn.f32x2 %0, %1, %2;" : "=l"(r) : "l"(F2U(a)), "l"(F2U(b)));
    return U2F(r);
}
__device__ __forceinline__ float2 sub2(float2 a, float2 b){   // a - b == fma(b,-1,a), exact
    const ull N1 = 0xBF800000BF800000ULL;
    ull r; asm("fma.rn.f32x2 %0, %1, %2, %3;" : "=l"(r) : "l"(F2U(b)), "l"(N1), "l"(F2U(a)));
    return U2F(r);
}
__device__ __forceinline__ float2 fma2(ull a, ull b, float2 c){
    ull r; asm("fma.rn.f32x2 %0, %1, %2, %3;" : "=l"(r) : "l"(a), "l"(b), "l"(F2U(c)));
    return U2F(r);
}
__device__ __forceinline__ ull pkxx(float2 a){
    ull r; asm("mov.b64 %0, {%1,%2};" : "=l"(r) : "f"(a.x), "f"(a.x)); return r;
}
__device__ __forceinline__ ull pkny(float2 a){
    ull r; asm("mov.b64 %0, {%1,%2};" : "=l"(r) : "f"(-a.y), "f"(a.y)); return r;
}

// ----------------------------- complex helpers -----------------------------
__device__ __forceinline__ float2 cmul(float2 a, float2 b){
    return make_float2(fmaf(a.x,b.x,-a.y*b.y), fmaf(a.x,b.y, a.y*b.x));
}
__device__ __forceinline__ float2 cfma(float2 r, float2 a, float2 w){
    r.x = fmaf(a.x,w.x, fmaf(-a.y,w.y,r.x));
    r.y = fmaf(a.x,w.y, fmaf( a.y,w.x,r.y));
    return r;
}
template<bool INV>
__device__ __forceinline__ float2 TW(int m){   // W400^m (conj if INV)
    float2 v = g_w400[m];
    if (INV) v.y = -v.y;
    return v;
}

// ----------------------------- FFT-20 (registers, packed f32x2): n=20 --------------
// HZ:   inputs a[5..14] are identically zero (never read).
// CROP: only outputs k in {0..4, 15..19} are produced (a[5..14] left garbage).
template<bool INV, bool HZ, bool CROP>
__device__ __forceinline__ void fft20(float2* a){
    float2 t[20];
    #pragma unroll
    for (int j2=0;j2<5;j2++){
        float2 y0,y1,y2,y3;
        if (HZ){
            float2 x0=a[j2], x3=a[15+j2];
            y0 = add2(x0,x3);
            y2 = sub2(x0,x3);
            if (!INV){ y1 = make_float2(x0.x - x3.y, x0.y + x3.x);
                       y3 = make_float2(x0.x + x3.y, x0.y - x3.x); }
            else     { y1 = make_float2(x0.x + x3.y, x0.y - x3.x);
                       y3 = make_float2(x0.x - x3.y, x0.y + x3.x); }
        } else {
            float2 x0=a[j2], x1=a[5+j2], x2=a[10+j2], x3=a[15+j2];
            float2 s02=add2(x0,x2), d02=sub2(x0,x2);
            float2 s13=add2(x1,x3), d13=sub2(x1,x3);
            y0=add2(s02,s13);
            y2=sub2(s02,s13);
            if (!INV){ y1=make_float2(d02.x+d13.y, d02.y-d13.x);
                       y3=make_float2(d02.x-d13.y, d02.y+d13.x); }
            else     { y1=make_float2(d02.x-d13.y, d02.y+d13.x);
                       y3=make_float2(d02.x+d13.y, d02.y-d13.x); }
        }
        t[j2] = y0;
        if (j2 == 0){               // W^0 == (1,0): skip identity multiplies
            t[5]  = y1;
            t[10] = y2;
            t[15] = y3;
        } else {
            t[5+j2]  = cmul(y1, TW<INV>(20*j2));
            t[10+j2] = cmul(y2, TW<INV>(40*j2));
            t[15+j2] = cmul(y3, TW<INV>(60*j2));
        }
    }
    const float C1f= 0.30901699437494742f, S1f=0.95105651629515357f;
    const float C2f=-0.80901699437494745f, S2f=0.58778525229247313f;
    const float si = INV ? 1.f : -1.f;
    const float2 w1=make_float2(C1f, si*S1f), w2=make_float2(C2f, si*S2f);
    const float2 w3=make_float2(C2f,-si*S2f), w4=make_float2(C1f,-si*S1f);
    ull W1p=F2U(w1), W2p=F2U(w2), W3p=F2U(w3), W4p=F2U(w4);
    ull W1s=F2U(make_float2(w1.y,w1.x)), W2s=F2U(make_float2(w2.y,w2.x));
    ull W3s=F2U(make_float2(w3.y,w3.x)), W4s=F2U(make_float2(w4.y,w4.x));
    #pragma unroll
    for (int k1=0;k1<4;k1++){
        float2 b0=t[k1*5], b1=t[k1*5+1], b2=t[k1*5+2], b3=t[k1*5+3], b4=t[k1*5+4];
        a[k1] = add2(add2(add2(add2(b0,b1),b2),b3),b4);
        if (!CROP){
            ull b1x=pkxx(b1), b1n=pkny(b1);
            ull b2x=pkxx(b2), b2n=pkny(b2);
            ull b3x=pkxx(b3), b3n=pkny(b3);
            ull b4x=pkxx(b4), b4n=pkny(b4);
            float2 y1 = fma2(b1x,W1p, fma2(b1n,W1s, b0));
            y1 = fma2(b2x,W2p, fma2(b2n,W2s, y1));
            y1 = fma2(b3x,W3p, fma2(b3n,W3s, y1));
            y1 = fma2(b4x,W4p, fma2(b4n,W4s, y1));
            a[k1+4]=y1;
            float2 y2 = fma2(b1x,W2p, fma2(b1n,W2s, b0));
            y2 = fma2(b2x,W4p, fma2(b2n,W4s, y2));
            y2 = fma2(b3x,W1p, fma2(b3n,W1s, y2));
            y2 = fma2(b4x,W3p, fma2(b4n,W3s, y2));
            a[k1+8]=y2;
            float2 y3 = fma2(b1x,W3p, fma2(b1n,W3s, b0));
            y3 = fma2(b2x,W1p, fma2(b2n,W1s, y3));
            y3 = fma2(b3x,W4p, fma2(b3n,W4s, y3));
            y3 = fma2(b4x,W2p, fma2(b4n,W2s, y3));
            a[k1+12]=y3;
            float2 y4 = fma2(b1x,W4p, fma2(b1n,W4s, b0));
            y4 = fma2(b2x,W3p, fma2(b2n,W3s, y4));
            y4 = fma2(b3x,W2p, fma2(b3n,W2s, y4));
            y4 = fma2(b4x,W1p, fma2(b4n,W1s, y4));
            a[k1+16]=y4;
        } else {
            if (k1==0){
                float2 y1=b0; y1=cfma(y1,b1,w1); y1=cfma(y1,b2,w2); y1=cfma(y1,b3,w3); y1=cfma(y1,b4,w4);
                a[4]=y1;
            }
            if (k1==3){
                float2 y3=b0; y3=cfma(y3,b1,w3); y3=cfma(y3,b2,w1); y3=cfma(y3,b3,w4); y3=cfma(y3,b4,w2);
                a[15]=y3;
            }
            float2 y4=b0; y4=cfma(y4,b1,w4); y4=cfma(y4,b2,w3); y4=cfma(y4,b3,w2); y4=cfma(y4,b4,w1);
            a[k1+16]=y4;
        }
    }
}

// ----------------------------- incremental inter-stage twiddles --------------------
template<bool INV>
__device__ __forceinline__ void twiddle_apply(float2* r, int lane){
    float2 Wa = TW<INV>(lane);
    float2 A5 = TW<INV>(5*lane);
    float2 A10= TW<INV>(10*lane);
    float2 A15= TW<INV>(15*lane);
    float2 W2 = cmul(Wa,Wa);
    float2 W3 = cmul(W2,Wa);
    float2 W4 = cmul(W3,Wa);
    r[1]=cmul(r[1],Wa);  r[2]=cmul(r[2],W2);
    r[3]=cmul(r[3],W3);  r[4]=cmul(r[4],W4);
    r[5]=cmul(r[5],A5);
    r[6]=cmul(r[6],cmul(A5,Wa));   r[7]=cmul(r[7],cmul(A5,W2));
    r[8]=cmul(r[8],cmul(A5,W3));   r[9]=cmul(r[9],cmul(A5,W4));
    r[10]=cmul(r[10],A10);
    r[11]=cmul(r[11],cmul(A10,Wa)); r[12]=cmul(r[12],cmul(A10,W2));
    r[13]=cmul(r[13],cmul(A10,W3)); r[14]=cmul(r[14],cmul(A10,W4));
    r[15]=cmul(r[15],A15);
    r[16]=cmul(r[16],cmul(A15,Wa)); r[17]=cmul(r[17],cmul(A15,W2));
    r[18]=cmul(r[18],cmul(A15,W3)); r[19]=cmul(r[19],cmul(A15,W4));
}

// ----------------------------- FFT-400 (warp, 20 active lanes): 20x20 four-step ----
// (generic version kept for kA0 / kCF)
template<bool INV, bool HZ, bool CROP>
__device__ void fft400(float2* __restrict__ lin, float2* __restrict__ tmp, int lane){
    __syncwarp();
    float2 r[20];
    if (lane < 20){
        if (HZ){
            #pragma unroll
            for (int j1=0;j1<5;j1++)  r[j1]=lin[j1*20+lane];
            #pragma unroll
            for (int j1=15;j1<20;j1++) r[j1]=lin[j1*20+lane];
        } else {
            #pragma unroll
            for (int j1=0;j1<20;j1++) r[j1]=lin[j1*20+lane];
        }
        fft20<INV,HZ,false>(r);
        twiddle_apply<INV>(r,lane);
        #pragma unroll
        for (int k1=0;k1<20;k1++) tmp[k1*21+lane]=r[k1];
    }
    __syncwarp();
    if (lane < 20){
        #pragma unroll
        for (int j2=0;j2<20;j2++) r[j2]=tmp[lane*21+j2];
        fft20<INV,false,CROP>(r);
        #pragma unroll
        for (int k2=0;k2<20;k2++)
            if (!CROP || k2<5 || k2>=15) lin[k2*20+lane]=r[k2];
    }
    __syncwarp();
}

// ----------------------------- kB fused transform: fwd FFT -> *H -> inv FFT --------
__device__ void fftB_fused(float2* __restrict__ col, float2* __restrict__ tmp,
                           int lane, const float2* __restrict__ ht){
    __syncwarp();
    float2 r[20];
    if (lane < 20){
        #pragma unroll
        for (int j1=0;j1<5;j1++)  r[j1]=col[j1*20+lane];
        #pragma unroll
        for (int j1=15;j1<20;j1++) r[j1]=col[j1*20+lane];
        fft20<false,true,false>(r);          // fwd stage1 (half-zero)
        twiddle_apply<false>(r,lane);
        #pragma unroll
        for (int k1=0;k1<20;k1++) tmp[k1*21+lane]=r[k1];
    }
    __syncwarp();
    if (lane < 20){
        #pragma unroll
        for (int j2=0;j2<20;j2++) r[j2]=tmp[lane*21+j2];
    }
    __syncwarp();                            // tmp reads done before overwrite
    if (lane < 20){
        fft20<false,false,false>(r);         // fwd stage2 -> X at pos 20m+lane
        #pragma unroll
        for (int j1=0;j1<20;j1++) r[j1]=cmul(r[j1], ht[j1*20+lane]);  // *H (pre-scaled)
        fft20<true,false,false>(r);          // inv stage1
        twiddle_apply<true>(r,lane);
        #pragma unroll
        for (int k1=0;k1<20;k1++) tmp[k1*21+lane]=r[k1];
    }
    __syncwarp();
    if (lane < 20){
        #pragma unroll
        for (int j2=0;j2<20;j2++) r[j2]=tmp[lane*21+j2];
        fft20<true,false,true>(r);           // inv stage2, cropped
        #pragma unroll
        for (int k2=0;k2<20;k2++)
            if (k2<5 || k2>=15) col[k2*20+lane]=r[k2];
    }
    __syncwarp();
}

// ----------------------------- kC fused transform: inv FFT -> phasor -> fwd FFT ----
__device__ void fftC_fused(float2* __restrict__ lin, float2* __restrict__ tmp,
                           int lane, const float2* __restrict__ ph){
    __syncwarp();
    float2 r[20];
    if (lane < 20){
        #pragma unroll
        for (int j1=0;j1<20;j1++) r[j1]=lin[j1*20+lane];
        fft20<true,false,false>(r);          // inv stage1
        twiddle_apply<true>(r,lane);
        #pragma unroll
        for (int k1=0;k1<20;k1++) tmp[k1*21+lane]=r[k1];
    }
    __syncwarp();
    if (lane < 20){
        #pragma unroll
        for (int j2=0;j2<20;j2++) r[j2]=tmp[lane*21+j2];
    }
    __syncwarp();                            // tmp reads done before overwrite
    if (lane < 20){
        fft20<true,false,true>(r);           // inv stage2 CROP: corners valid
        if (ph){
            #pragma unroll
            for (int k2=0;k2<5;k2++)   r[k2] = cmul(r[k2], ph[20*k2+lane+100]);
            #pragma unroll
            for (int k2=15;k2<20;k2++) r[k2] = cmul(r[k2], ph[20*k2+lane-300]);
        } else {
            const float sc = 1.f/400.f;
            #pragma unroll
            for (int k2=0;k2<5;k2++){  r[k2].x*=sc; r[k2].y*=sc; }
            #pragma unroll
            for (int k2=15;k2<20;k2++){ r[k2].x*=sc; r[k2].y*=sc; }
        }
        fft20<false,true,false>(r);          // fwd stage1 (half-zero corners)
        twiddle_apply<false>(r,lane);
        #pragma unroll
        for (int k1=0;k1<20;k1++) tmp[k1*21+lane]=r[k1];
    }
    __syncwarp();
    if (lane < 20){
        #pragma unroll
        for (int j2=0;j2<20;j2++) r[j2]=tmp[lane*21+j2];
        fft20<false,false,false>(r);         // fwd stage2
        #pragma unroll
        for (int k2=0;k2<20;k2++) lin[k2*20+lane]=r[k2];
    }
    __syncwarp();
}

#define WPB 4  // warps (transforms) per block for row-FFT kernels

// ----------------------------- init: twiddles + zero histogram -----------------------------
__global__ void kInit(float* out){
    int k = threadIdx.x;
    if (k < 400){
        double ang = -2.0*PI_D*(double)k/400.0;
        g_w400[k] = make_float2((float)cos(ang), (float)sin(ang));
    }
    if (k < 11) out[1250+k] = 0.f;
}

// ----------------------------- precompute layer phasors (pre-scaled by 1/400) ------
__global__ void kPrep(const float* __restrict__ phase){
    int idx = blockIdx.x*256 + threadIdx.x;
    if (idx >= 4*40000) return;
    float p = phase[idx];
    float sv, cv;
    sincospif(2.f*(sinf(p)+1.f), &sv, &cv);   // e^{i*2*pi*(sin(p)+1)}
    const float sc = 1.f/400.f;
    g_PH[idx] = make_float2(cv*sc, sv*sc);
}

// ----------------------------- transpose transfer functions (pre-scaled by 1/400) --
__global__ void kHT(const float2* __restrict__ t0, const float2* __restrict__ t1,
                    const float2* __restrict__ t2){
    __shared__ float2 tile[32][33];
    int m = blockIdx.z;
    const float2* src = (m==0)? t0 : (m==1)? t1 : t2;
    int r0 = blockIdx.y*32, k0 = blockIdx.x*32;
    int tx = threadIdx.x, ty = threadIdx.y;   // 32 x 8
    const float sc = 1.f/400.f;
    for (int yy=ty; yy<32; yy+=8){
        int r = r0+yy, k = k0+tx;
        if (r<400 && k<400) tile[yy][tx] = src[r*400+k];
    }
    __syncthreads();
    for (int yy=ty; yy<32; yy+=8){
        int k = k0+yy, r = r0+tx;
        if (r<400 && k<400){
            float2 v = tile[tx][yy];
            g_HT[(size_t)m*160000 + k*400 + r] = make_float2(v.x*sc, v.y*sc);
        }
    }
}

// ----------------------------- W1 transpose (tiled) + row sums -----------------------------
__global__ void kT(const float* __restrict__ W1){
    __shared__ float tile[32][33];
    int p0 = blockIdx.x*32, h0 = blockIdx.y*32;
    int tx = threadIdx.x, ty = threadIdx.y;   // 32 x 8
    for (int yy=ty; yy<32; yy+=8){
        int hh = h0+yy, p = p0+tx;
        if (hh<512 && p<625) tile[yy][tx] = W1[hh*625+p];
    }
    __syncthreads();
    for (int yy=ty; yy<32; yy+=8){
        int p = p0+yy, hh = h0+tx;
        if (p<625 && hh<512) g_W1T[p*512+hh] = tile[tx][yy];
    }
}
__global__ void kR1(const float* __restrict__ W1){   // grid 512, block 128
    __shared__ float red[128];
    int hh = blockIdx.x, tid = threadIdx.x;
    float s = 0.f;
    for (int p=tid; p<625; p+=128) s += W1[hh*625+p];
    red[tid] = s;
    __syncthreads();
    for (int st=64; st>0; st>>=1){
        if (tid<st) red[tid]+=red[tid+st];
        __syncthreads();
    }
    if (tid==0) g_R1[hh] = red[0];
}

// ----------------------------- A0: real input, 2 rows packed per complex FFT --------
__global__ void kA0(const float* __restrict__ x){   // grid 800, block 128
    __shared__ __align__(16) float2 s_lin[WPB][400];
    __shared__ float2 s_tmp[WPB][421];
    int w = threadIdx.x>>5, lane = threadIdx.x&31;
    int idx = blockIdx.x*WPB + w;                   // 0..3199 row-pairs
    int b = idx/100, pr = idx%100;
    int c0 = 2*pr, c1 = 2*pr+1;
    int i0 = (c0<100)? c0+100 : c0-100;             // logical rows
    int i1 = (c1<100)? c1+100 : c1-100;
    const float4* x0r4 = (const float4*)(x + ((size_t)b*200 + i0)*200);
    const float4* x1r4 = (const float4*)(x + ((size_t)b*200 + i1)*200);
    float2* lin = s_lin[w]; float2* tmp = s_tmp[w];
    if (lane < 25){
        float4 a0 = x0r4[25+lane], b0 = x1r4[25+lane];   // x[100..199] -> lin[0..99]
        lin[4*lane  ] = make_float2(a0.x, b0.x);
        lin[4*lane+1] = make_float2(a0.y, b0.y);
        lin[4*lane+2] = make_float2(a0.z, b0.z);
        lin[4*lane+3] = make_float2(a0.w, b0.w);
        float4 a1 = x0r4[lane],    b1 = x1r4[lane];      // x[0..99] -> lin[300..399]
        lin[300+4*lane  ] = make_float2(a1.x, b1.x);
        lin[300+4*lane+1] = make_float2(a1.y, b1.y);
        lin[300+4*lane+2] = make_float2(a1.z, b1.z);
        lin[300+4*lane+3] = make_float2(a1.w, b1.w);
    }
    fft400<false,true,false>(lin,tmp,lane);
    float2* row0 = g_S + ((size_t)b*200+c0)*400;
    float2* row1 = g_S + ((size_t)b*200+c1)*400;
    for (int k=lane; k<400; k+=32){
        float2 Zk = lin[k];
        float2 Zr = lin[(400-k) & 399];   // (400-k)%400; k=0 -> 0
        row0[k] = make_float2(0.5f*(Zk.x+Zr.x),  0.5f*(Zk.y-Zr.y));
        row1[k] = make_float2(0.5f*(Zk.y+Zr.y), -0.5f*(Zk.x-Zr.x));
    }
}

// ----------------------------- B (warp-private): fused col FFT*H*IFFT ---------------
__global__ void __launch_bounds__(128) kB(int hm){
    __shared__ __align__(16) float2 colb[8][401];
    __shared__ float2 tmpb[4][421];
    int b  = blockIdx.x / 50;
    int k0 = (blockIdx.x % 50) * 8;
    int tid = threadIdx.x;
    const float4* Sb4 = (const float4*)(g_S + (size_t)b*200*400);
    const float2* HT = g_HT + (size_t)hm*160000;

    // stage in (float4 = 2 complex): col[kl][r], r in [0,100) U [300,400)
    for (int idx=tid; idx<800; idx+=128){
        int c = idx>>2, q = idx&3;
        float4 v = Sb4[c*200 + (k0>>1) + q];
        int r = (c<100)? c : c+200;
        colb[2*q  ][r] = make_float2(v.x,v.y);
        colb[2*q+1][r] = make_float2(v.z,v.w);
    }
    __syncthreads();

    int w = tid>>5, lane = tid&31;
    fftB_fused(colb[2*w  ], tmpb[w], lane, HT + (size_t)(k0+2*w  )*400);
    fftB_fused(colb[2*w+1], tmpb[w], lane, HT + (size_t)(k0+2*w+1)*400);
    __syncthreads();

    // stage out (float4), crop rows (no scale: folded into HT)
    float4* S2b4 = (float4*)(g_S2 + (size_t)b*200*400);
    for (int idx=tid; idx<800; idx+=128){
        int c = idx>>2, q = idx&3;
        int r = (c<100)? c : c+200;
        float2 v0 = colb[2*q  ][r];
        float2 v1 = colb[2*q+1][r];
        S2b4[c*200 + (k0>>1) + q] = make_float4(v0.x, v0.y, v1.x, v1.y);
    }
}

// ----------------------------- C: fused row IFFT -> phasor -> row FFT ---------------
__global__ void kC(int l){   // l < 0: no phasor (first boundary)
    __shared__ __align__(16) float2 s_lin[WPB][400];
    __shared__ float2 s_tmp[WPB][421];
    int w = threadIdx.x>>5, lane = threadIdx.x&31;
    int idx = blockIdx.x*WPB + w;
    int b = idx/200, c = idx%200;
    float2* lin = s_lin[w]; float2* tmp = s_tmp[w];
    const float4* S4 = (const float4*)(g_S2 + ((size_t)b*200+c)*400);
    float4* lin4 = (float4*)lin;
    for (int m4=lane;m4<200;m4+=32) lin4[m4]=S4[m4];
    int i = (c<100)? c+100 : c-100;                 // logical row
    const float2* phrow = (l>=0)? (g_PH + (size_t)l*40000 + i*200) : nullptr;
    fftC_fused(lin,tmp,lane,phrow);
    float4* out4 = (float4*)(g_S + ((size_t)b*200+c)*400);
    const float4* l4 = (const float4*)lin;
    for (int m4=lane;m4<200;m4+=32) out4[m4]=l4[m4];
}

// ----------------------------- CF: row IFFT -> intensity -> horizontal 8-sums ------
__global__ void kCF(){
    __shared__ __align__(16) float2 s_lin[WPB][400];
    __shared__ float2 s_tmp[WPB][421];
    int w = threadIdx.x>>5, lane = threadIdx.x&31;
    int idx = blockIdx.x*WPB + w;
    int b = idx/200, c = idx%200;
    float2* lin = s_lin[w]; float2* tmp = s_tmp[w];
    const float4* S4 = (const float4*)(g_S2 + ((size_t)b*200+c)*400);
    float4* lin4 = (float4*)lin;
    for (int m4=lane;m4<200;m4+=32) lin4[m4]=S4[m4];
    fft400<true,false,true>(lin,tmp,lane);          // cropped inverse
    int i = (c<100)? c+100 : c-100;
    float* pbuf = (float*)tmp;                      // tmp is free now; 200 floats
    const float sc = 1.f/400.f;
    for (int cc=lane;cc<200;cc+=32){
        int rc = (cc<100)? cc : cc+200;
        int j  = (cc<100)? cc+100 : cc-100;
        float vx = lin[rc].x*sc, vy = lin[rc].y*sc;
        pbuf[j] = vx*vx + vy*vy;
    }
    __syncwarp();
    if (lane < 25){
        float s = 0.f;
        #pragma unroll
        for (int v=0; v<8; v++) s += pbuf[lane*8+v];
        g_Pp[((size_t)b*200+i)*25 + lane] = s;
    }
}

// ----------------------------- pooling: vertical sum of 8 partials -> [p][b] -------
__global__ void kPool(){
    int idx = blockIdx.x*256 + threadIdx.x;
    if (idx >= 20000) return;
    int b = idx / 625, p = idx % 625;
    int mi = p/25, mj = p%25;
    const float* base = g_Pp + ((size_t)b*200 + mi*8)*25 + mj;
    float s = 0.f;
    #pragma unroll
    for (int u=0;u<8;u++) s += base[u*25];
    g_pool[p*32+b] = s*(1.f/64.f);
}

// ----------------------------- per-window MLP + voting -----------------------------
#define HSTR 513    // padded hid stride (bank-conflict-free)
__global__ void __launch_bounds__(256) kWin(
                     const float* __restrict__ b1, const float* __restrict__ W2,
                     const float* __restrict__ b2, const float* __restrict__ gamma,
                     const float* __restrict__ beta, float* __restrict__ out)
{
    extern __shared__ float dsm[];
    float* swin = dsm;                    // [cell][b] up to 25*32
    float* hid  = dsm + 800;              // [b][hh] 32*HSTR
    float* lg   = dsm + 800 + 32*HSTR;    // [b][o]  32*10
    __shared__ double red1[256], red2[256];
    __shared__ int   pidx[25];
    __shared__ float s_inv, s_c0;
    __shared__ int   s_a[32];
    __shared__ float s_delta[32];

    int wI = blockIdx.x;
    int i = wI/25, j = wI%25;
    int wr = min(5, 25-i), wc = min(5, 25-j);
    int cells = wr*wc;
    int tid = threadIdx.x;
    if (tid < cells) pidx[tid] = (i + tid/wc)*25 + (j + tid%wc);
    __syncthreads();

    double s1 = 0.0, s2 = 0.0;
    for (int q=tid; q<cells*32; q+=256){
        int cell = q>>5, b = q&31;
        float v = g_pool[pidx[cell]*32 + b];
        swin[q] = v;
        s1 += v; s2 += (double)v*(double)v;
    }
    red1[tid]=s1; red2[tid]=s2;
    __syncthreads();
    for (int st=128; st>0; st>>=1){
        if (tid<st){ red1[tid]+=red1[tid+st]; red2[tid]+=red2[tid+st]; }
        __syncthreads();
    }
    if (tid == 0){
        double mu  = red1[0]/20000.0;
        double var = red2[0]/20000.0 - mu*mu;
        float inv = gamma[0]/(float)sqrt(var + 1e-5);
        s_inv = inv;
        s_c0  = beta[0] - (float)mu*inv;
    }
    __syncthreads();
    float inv = s_inv, c0 = s_c0;

    // hid[b][hh] = relu(c0*R1 + inv*<win,W1win> + b1); 8 batches per thread.
    for (int it=0; it<8; it++){
        int task = it*256 + tid;          // 2048 tasks = 4 bgroups x 512 hh
        int hh = task & 511, bg = task >> 9;
        float acc[8];
        #pragma unroll
        for (int u=0;u<8;u++) acc[u]=0.f;
        for (int cell=0; cell<cells; cell++){
            float wv = g_W1T[pidx[cell]*512+hh];
            const float* sw = swin + cell*32 + bg*8;
            #pragma unroll
            for (int u=0;u<8;u++) acc[u] = fmaf(sw[u], wv, acc[u]);
        }
        float base = fmaf(c0, g_R1[hh], b1[hh]);
        #pragma unroll
        for (int u=0;u<8;u++){
            float pre = fmaf(inv, acc[u], base);
            hid[(bg*8+u)*HSTR + hh] = fmaxf(pre, 0.f);
        }
    }
    __syncthreads();

    for (int t=tid; t<320; t+=256){
        int b = t/10, oo = t%10;
        float acc = b2[oo];
        const float* hb = hid + b*HSTR;
        const float* wv = W2 + oo*512;
        for (int hh=0; hh<512; hh++) acc = fmaf(hb[hh], wv[hh], acc);
        lg[b*10+oo] = acc;
    }
    __syncthreads();

    if (tid < 32){
        int b = tid;
        float lmax = lg[b*10], lmin = lg[b*10];
        int am = 0;
        for (int oo=1;oo<10;oo++){
            float v = lg[b*10+oo];
            if (v > lmax){ lmax = v; am = oo; }
            if (v < lmin)  lmin = v;
        }
        float se = 0.f;
        for (int oo=0;oo<10;oo++) se += expf(lg[b*10+oo]-lmax);
        s_a[b] = am;
        s_delta[b] = (1.f - expf(lmin-lmax))/se;  // pmax - pmin
    }
    __syncthreads();
    if (tid == 0){
        int votes[11];
        for (int k=0;k<11;k++) votes[k]=0;
        for (int b=0;b<32;b++) votes[s_a[b]]++;
        int f0 = 0, best = votes[0];
        for (int k=1;k<11;k++) if (votes[k] > best){ best = votes[k]; f0 = k; }
        float sum = 0.f; int cnt = 0;
        for (int b=0;b<32;b++)
            if (s_a[b]==f0 && s_delta[b]!=0.f){ sum += s_delta[b]; cnt++; }
        int fin;
        if (cnt > 0){ float d1 = sum/(float)cnt; fin = (d1 < 0.2f) ? 0 : f0+1; }
        else fin = f0+1;   // delta1 = NaN; NaN < THR is false
        out[wI]       = (fin==0) ? 0.f : (float)fin;
        out[625+wI]   = (fin!=0) ? 1.f : 0.f;
        atomicAdd(&out[1250+fin], 1.0f);   // exact integer counts -> deterministic
    }
}

// ----------------------------- launch -----------------------------
extern "C" void kernel_launch(void* const* d_in, const int* in_sizes, int n_in,
                              void* d_out, int out_size)
{
    int o = (n_in >= 12 && in_sizes[1] == 1) ? 1 : 0;  // skip batch_size scalar if present
    const float*  x     = (const float*) d_in[0];
    const float2* h     = (const float2*)d_in[1+o];
    const float2* h_pro = (const float2*)d_in[2+o];
    const float2* h_det = (const float2*)d_in[3+o];
    const float*  phase = (const float*) d_in[4+o];
    const float*  W1    = (const float*) d_in[5+o];
    const float*  b1    = (const float*) d_in[6+o];
    const float*  W2    = (const float*) d_in[7+o];
    const float*  b2    = (const float*) d_in[8+o];
    const float*  gamma = (const float*) d_in[9+o];
    const float*  beta  = (const float*) d_in[10+o];
    float* out = (float*)d_out;

    cudaFuncSetAttribute(kWin, cudaFuncAttributeMaxDynamicSharedMemorySize,
                         (800 + 32*HSTR + 320)*4);

    // Order: kB stays the 4th launch (ncu's captured slot) for diagnostics.
    kInit<<<1,512>>>(out);
    kHT <<<dim3(13,13,3),dim3(32,8)>>>(h_pro, h, h_det);   // [0]=h_pro, [1]=h, [2]=h_det
    kA0 <<<800,128>>>(x);                  // 2 rows per FFT (real packing)
    kB  <<<1600,128>>>(0);                 // h_pro  <-- profiled slot
    kPrep<<<625,256>>>(phase);
    kT  <<<dim3(20,16),dim3(32,8)>>>(W1);
    kR1 <<<512,128>>>(W1);
    kC  <<<1600,128>>>(-1);
    for (int l=0; l<4; l++){
        kB <<<1600,128>>>(1);              // h (transposed once, reused 4x)
        kC <<<1600,128>>>(l);
    }
    kB  <<<1600,128>>>(2);                 // h_det
    kCF <<<1600,128>>>();

    kPool<<<79,256>>>();

    kWin<<<625,256,(800 + 32*HSTR + 320)*4>>>(b1, W2, b2, gamma, beta, out);
}

// round 15
// speedup vs baseline: 1.0950x; 1.0447x over previous
#include <cuda_runtime.h>
#include <math.h>

#define PI_D 3.14159265358979323846
typedef unsigned long long ull;

// ----------------------------- scratch (device globals) -----------------------------
__device__ __align__(16) float2 g_S [32*200*400];   // row-FFT'd field, compact rows
__device__ __align__(16) float2 g_S2[32*200*400];   // after col FFT * trans * IFFT
__device__ float2 g_HT[3*400*400];    // transposed transfer functions [m][k][r], pre-scaled 1/400
__device__ float2 g_PH[4*200*200];    // precomputed layer phasors [l][i][j], pre-scaled 1/400
__device__ float  g_Pp[32*200*25];    // horizontal 8-sums of intensity [b][i][j8]
__device__ float  g_pool[625*32];     // pooled [p][b]
__device__ float  g_W1T[625*512];     // W1 transposed [p][hh]
__device__ float  g_R1[512];          // row sums of W1
__device__ float2 g_w400[400];        // e^{-2*pi*i*k/400}, fp64-initialized

// ----------------------------- packed f32x2 helpers (sm_100+) -----------------------
__device__ __forceinline__ ull F2U(float2 v){
    ull r; asm("mov.b64 %0, {%1,%2};" : "=l"(r) : "f"(v.x), "f"(v.y)); return r;
}
__device__ __forceinline__ float2 U2F(ull v){
    float2 r; asm("mov.b64 {%0,%1}, %2;" : "=f"(r.x), "=f"(r.y) : "l"(v)); return r;
}
__device__ __forceinline__ float2 add2(float2 a, float2 b){
    ull r; asm("add.rn.f32x2 %0, %1, %2;" : "=l"(r) : "l"(F2U(a)), "l"(F2U(b)));
    return U2F(r);
}
__device__ __forceinline__ float2 sub2(float2 a, float2 b){   // a - b == fma(b,-1,a), exact
    const ull N1 = 0xBF800000BF800000ULL;
    ull r; asm("fma.rn.f32x2 %0, %1, %2, %3;" : "=l"(r) : "l"(F2U(b)), "l"(N1), "l"(F2U(a)));
    return U2F(r);
}
__device__ __forceinline__ float2 fma2(ull a, ull b, float2 c){
    ull r; asm("fma.rn.f32x2 %0, %1, %2, %3;" : "=l"(r) : "l"(a), "l"(b), "l"(F2U(c)));
    return U2F(r);
}
__device__ __forceinline__ ull pkxx(float2 a){
    ull r; asm("mov.b64 %0, {%1,%2};" : "=l"(r) : "f"(a.x), "f"(a.x)); return r;
}
__device__ __forceinline__ ull pkny(float2 a){
    ull r; asm("mov.b64 %0, {%1,%2};" : "=l"(r) : "f"(-a.y), "f"(a.y)); return r;
}
__device__ __forceinline__ ull pks(float a){
    ull r; asm("mov.b64 %0, {%1,%1};" : "=l"(r) : "f"(a)); return r;
}
__device__ __forceinline__ ull pk2f(float x, float y){
    ull r; asm("mov.b64 %0, {%1,%2};" : "=l"(r) : "f"(x), "f"(y)); return r;
}
// ull-domain packed math
__device__ __forceinline__ ull add2u(ull a, ull b){
    ull r; asm("add.rn.f32x2 %0, %1, %2;" : "=l"(r) : "l"(a), "l"(b)); return r;
}
__device__ __forceinline__ ull mul2u(ull a, ull b){
    ull r; asm("mul.rn.f32x2 %0, %1, %2;" : "=l"(r) : "l"(a), "l"(b)); return r;
}
__device__ __forceinline__ ull fma2u(ull a, ull b, ull c){
    ull r; asm("fma.rn.f32x2 %0, %1, %2, %3;" : "=l"(r) : "l"(a), "l"(b), "l"(c)); return r;
}
__device__ __forceinline__ ull sub2u(ull a, ull b){
    const ull N1 = 0xBF800000BF800000ULL;
    return fma2u(b, N1, a);
}

// ----------------------------- complex helpers -----------------------------
__device__ __forceinline__ float2 cmul(float2 a, float2 b){
    return make_float2(fmaf(a.x,b.x,-a.y*b.y), fmaf(a.x,b.y, a.y*b.x));
}
__device__ __forceinline__ float2 cfma(float2 r, float2 a, float2 w){
    r.x = fmaf(a.x,w.x, fmaf(-a.y,w.y,r.x));
    r.y = fmaf(a.x,w.y, fmaf( a.y,w.x,r.y));
    return r;
}
template<bool INV>
__device__ __forceinline__ float2 TW(int m){   // W400^m (conj if INV)
    float2 v = g_w400[m];
    if (INV) v.y = -v.y;
    return v;
}

// ----------------------------- SoA complex pair (2 columns per lane) ----------------
struct cp { ull R, I; };
__device__ __forceinline__ cp cpadd(cp a, cp b){ cp o; o.R=add2u(a.R,b.R); o.I=add2u(a.I,b.I); return o; }
__device__ __forceinline__ cp cpsub(cp a, cp b){ cp o; o.R=sub2u(a.R,b.R); o.I=sub2u(a.I,b.I); return o; }
// multiply by (possibly per-column) twiddle vectors wx, wy
__device__ __forceinline__ cp cpmulw(cp a, ull wx, ull wy){
    cp o;
    o.R = sub2u(mul2u(a.R,wx), mul2u(a.I,wy));
    o.I = fma2u(a.I, wx, mul2u(a.R,wy));
    return o;
}
// acc += b * w  with wx=(w.x,..), wy=(w.y,..), nwy=(-w.y,..)
__device__ __forceinline__ cp cpacc(cp acc, cp b, ull wx, ull wy, ull nwy){
    acc.R = fma2u(b.R, wx,  acc.R);
    acc.R = fma2u(b.I, nwy, acc.R);
    acc.I = fma2u(b.I, wx,  acc.I);
    acc.I = fma2u(b.R, wy,  acc.I);
    return acc;
}

// ----------------------------- FFT-20 pair (SoA, 2 columns at once) -----------------
template<bool INV, bool HZ, bool CROP>
__device__ __forceinline__ void fft20p(cp* a){
    cp t[20];
    #pragma unroll
    for (int j2=0;j2<5;j2++){
        cp y0,y1,y2,y3;
        if (HZ){
            cp x0=a[j2], x3=a[15+j2];
            y0 = cpadd(x0,x3);
            y2 = cpsub(x0,x3);
            if (!INV){ y1.R=add2u(x0.R,x3.I); y1.I=sub2u(x0.I,x3.R);
                       y3.R=sub2u(x0.R,x3.I); y3.I=add2u(x0.I,x3.R); }
            else     { y1.R=sub2u(x0.R,x3.I); y1.I=add2u(x0.I,x3.R);
                       y3.R=add2u(x0.R,x3.I); y3.I=sub2u(x0.I,x3.R); }
        } else {
            cp x0=a[j2], x1=a[5+j2], x2=a[10+j2], x3=a[15+j2];
            cp s02=cpadd(x0,x2), d02=cpsub(x0,x2);
            cp s13=cpadd(x1,x3), d13=cpsub(x1,x3);
            y0=cpadd(s02,s13);
            y2=cpsub(s02,s13);
            if (!INV){ y1.R=add2u(d02.R,d13.I); y1.I=sub2u(d02.I,d13.R);
                       y3.R=sub2u(d02.R,d13.I); y3.I=add2u(d02.I,d13.R); }
            else     { y1.R=sub2u(d02.R,d13.I); y1.I=add2u(d02.I,d13.R);
                       y3.R=add2u(d02.R,d13.I); y3.I=sub2u(d02.I,d13.R); }
        }
        t[j2]=y0;
        if (j2==0){ t[5]=y1; t[10]=y2; t[15]=y3; }
        else {
            float2 wA=TW<INV>(20*j2), wB=TW<INV>(40*j2), wC=TW<INV>(60*j2);
            t[5+j2]  = cpmulw(y1, pks(wA.x), pks(wA.y));
            t[10+j2] = cpmulw(y2, pks(wB.x), pks(wB.y));
            t[15+j2] = cpmulw(y3, pks(wC.x), pks(wC.y));
        }
    }
    const float C1f= 0.30901699437494742f, S1f=0.95105651629515357f;
    const float C2f=-0.80901699437494745f, S2f=0.58778525229247313f;
    const float si = INV ? 1.f : -1.f;
    ull w1x=pks(C1f),    w2x=pks(C2f);               // w3x==w2x, w4x==w1x
    ull w1y=pks(si*S1f), w2y=pks(si*S2f);
    ull w3y=pks(-si*S2f),w4y=pks(-si*S1f);
    // negated y's: n1y=-w1y=w4y, n2y=-w2y=w3y, n3y=-w3y=w2y, n4y=-w4y=w1y
    #pragma unroll
    for (int k1=0;k1<4;k1++){
        cp b0=t[k1*5], b1=t[k1*5+1], b2=t[k1*5+2], b3=t[k1*5+3], b4=t[k1*5+4];
        a[k1] = cpadd(cpadd(cpadd(cpadd(b0,b1),b2),b3),b4);
        if (!CROP || k1==0){
            cp y1=b0;
            y1=cpacc(y1,b1,w1x,w1y,w4y);
            y1=cpacc(y1,b2,w2x,w2y,w3y);
            y1=cpacc(y1,b3,w2x,w3y,w2y);
            y1=cpacc(y1,b4,w1x,w4y,w1y);
            a[k1+4]=y1;
        }
        if (!CROP){
            cp y2=b0;
            y2=cpacc(y2,b1,w2x,w2y,w3y);
            y2=cpacc(y2,b2,w1x,w4y,w1y);
            y2=cpacc(y2,b3,w1x,w1y,w4y);
            y2=cpacc(y2,b4,w2x,w3y,w2y);
            a[k1+8]=y2;
        }
        if (!CROP || k1==3){
            cp y3=b0;
            y3=cpacc(y3,b1,w2x,w3y,w2y);
            y3=cpacc(y3,b2,w1x,w1y,w4y);
            y3=cpacc(y3,b3,w1x,w4y,w1y);
            y3=cpacc(y3,b4,w2x,w2y,w3y);
            a[k1+12]=y3;
        }
        cp y4=b0;
        y4=cpacc(y4,b1,w1x,w4y,w1y);
        y4=cpacc(y4,b2,w2x,w3y,w2y);
        y4=cpacc(y4,b3,w2x,w2y,w3y);
        y4=cpacc(y4,b4,w1x,w1y,w4y);
        a[k1+16]=y4;
    }
}

// ----------------------------- pair inter-stage twiddles ----------------------------
template<bool INV>
__device__ __forceinline__ void twiddle_apply_p(cp* r, int lane){
    float2 Wa = TW<INV>(lane);
    float2 A5 = TW<INV>(5*lane);
    float2 A10= TW<INV>(10*lane);
    float2 A15= TW<INV>(15*lane);
    float2 W2 = cmul(Wa,Wa);
    float2 W3 = cmul(W2,Wa);
    float2 W4 = cmul(W3,Wa);
    #define APL(i,wexpr) { float2 _w=(wexpr); r[i]=cpmulw(r[i], pks(_w.x), pks(_w.y)); }
    APL(1,Wa)  APL(2,W2)  APL(3,W3)  APL(4,W4)
    APL(5,A5)
    APL(6,cmul(A5,Wa))   APL(7,cmul(A5,W2))   APL(8,cmul(A5,W3))   APL(9,cmul(A5,W4))
    APL(10,A10)
    APL(11,cmul(A10,Wa)) APL(12,cmul(A10,W2)) APL(13,cmul(A10,W3)) APL(14,cmul(A10,W4))
    APL(15,A15)
    APL(16,cmul(A15,Wa)) APL(17,cmul(A15,W2)) APL(18,cmul(A15,W3)) APL(19,cmul(A15,W4))
    #undef APL
}

// ----------------------------- scalar FFT-20 (kept for kA0/kC/kCF) ------------------
template<bool INV, bool HZ, bool CROP>
__device__ __forceinline__ void fft20(float2* a){
    float2 t[20];
    #pragma unroll
    for (int j2=0;j2<5;j2++){
        float2 y0,y1,y2,y3;
        if (HZ){
            float2 x0=a[j2], x3=a[15+j2];
            y0 = add2(x0,x3);
            y2 = sub2(x0,x3);
            if (!INV){ y1 = make_float2(x0.x - x3.y, x0.y + x3.x);
                       y3 = make_float2(x0.x + x3.y, x0.y - x3.x); }
            else     { y1 = make_float2(x0.x + x3.y, x0.y - x3.x);
                       y3 = make_float2(x0.x - x3.y, x0.y + x3.x); }
        } else {
            float2 x0=a[j2], x1=a[5+j2], x2=a[10+j2], x3=a[15+j2];
            float2 s02=add2(x0,x2), d02=sub2(x0,x2);
            float2 s13=add2(x1,x3), d13=sub2(x1,x3);
            y0=add2(s02,s13);
            y2=sub2(s02,s13);
            if (!INV){ y1=make_float2(d02.x+d13.y, d02.y-d13.x);
                       y3=make_float2(d02.x-d13.y, d02.y+d13.x); }
            else     { y1=make_float2(d02.x-d13.y, d02.y+d13.x);
                       y3=make_float2(d02.x+d13.y, d02.y-d13.x); }
        }
        t[j2] = y0;
        if (j2 == 0){
            t[5]  = y1;
            t[10] = y2;
            t[15] = y3;
        } else {
            t[5+j2]  = cmul(y1, TW<INV>(20*j2));
            t[10+j2] = cmul(y2, TW<INV>(40*j2));
            t[15+j2] = cmul(y3, TW<INV>(60*j2));
        }
    }
    const float C1f= 0.30901699437494742f, S1f=0.95105651629515357f;
    const float C2f=-0.80901699437494745f, S2f=0.58778525229247313f;
    const float si = INV ? 1.f : -1.f;
    const float2 w1=make_float2(C1f, si*S1f), w2=make_float2(C2f, si*S2f);
    const float2 w3=make_float2(C2f,-si*S2f), w4=make_float2(C1f,-si*S1f);
    ull W1p=F2U(w1), W2p=F2U(w2), W3p=F2U(w3), W4p=F2U(w4);
    ull W1s=F2U(make_float2(w1.y,w1.x)), W2s=F2U(make_float2(w2.y,w2.x));
    ull W3s=F2U(make_float2(w3.y,w3.x)), W4s=F2U(make_float2(w4.y,w4.x));
    #pragma unroll
    for (int k1=0;k1<4;k1++){
        float2 b0=t[k1*5], b1=t[k1*5+1], b2=t[k1*5+2], b3=t[k1*5+3], b4=t[k1*5+4];
        a[k1] = add2(add2(add2(add2(b0,b1),b2),b3),b4);
        if (!CROP){
            ull b1x=pkxx(b1), b1n=pkny(b1);
            ull b2x=pkxx(b2), b2n=pkny(b2);
            ull b3x=pkxx(b3), b3n=pkny(b3);
            ull b4x=pkxx(b4), b4n=pkny(b4);
            float2 y1 = fma2(b1x,W1p, fma2(b1n,W1s, b0));
            y1 = fma2(b2x,W2p, fma2(b2n,W2s, y1));
            y1 = fma2(b3x,W3p, fma2(b3n,W3s, y1));
            y1 = fma2(b4x,W4p, fma2(b4n,W4s, y1));
            a[k1+4]=y1;
            float2 y2 = fma2(b1x,W2p, fma2(b1n,W2s, b0));
            y2 = fma2(b2x,W4p, fma2(b2n,W4s, y2));
            y2 = fma2(b3x,W1p, fma2(b3n,W1s, y2));
            y2 = fma2(b4x,W3p, fma2(b4n,W3s, y2));
            a[k1+8]=y2;
            float2 y3 = fma2(b1x,W3p, fma2(b1n,W3s, b0));
            y3 = fma2(b2x,W1p, fma2(b2n,W1s, y3));
            y3 = fma2(b3x,W4p, fma2(b3n,W4s, y3));
            y3 = fma2(b4x,W2p, fma2(b4n,W2s, y3));
            a[k1+12]=y3;
            float2 y4 = fma2(b1x,W4p, fma2(b1n,W4s, b0));
            y4 = fma2(b2x,W3p, fma2(b2n,W3s, y4));
            y4 = fma2(b3x,W2p, fma2(b3n,W2s, y4));
            y4 = fma2(b4x,W1p, fma2(b4n,W1s, y4));
            a[k1+16]=y4;
        } else {
            if (k1==0){
                float2 y1=b0; y1=cfma(y1,b1,w1); y1=cfma(y1,b2,w2); y1=cfma(y1,b3,w3); y1=cfma(y1,b4,w4);
                a[4]=y1;
            }
            if (k1==3){
                float2 y3=b0; y3=cfma(y3,b1,w3); y3=cfma(y3,b2,w1); y3=cfma(y3,b3,w4); y3=cfma(y3,b4,w2);
                a[15]=y3;
            }
            float2 y4=b0; y4=cfma(y4,b1,w4); y4=cfma(y4,b2,w3); y4=cfma(y4,b3,w2); y4=cfma(y4,b4,w1);
            a[k1+16]=y4;
        }
    }
}

// ----------------------------- scalar inter-stage twiddles --------------------------
template<bool INV>
__device__ __forceinline__ void twiddle_apply(float2* r, int lane){
    float2 Wa = TW<INV>(lane);
    float2 A5 = TW<INV>(5*lane);
    float2 A10= TW<INV>(10*lane);
    float2 A15= TW<INV>(15*lane);
    float2 W2 = cmul(Wa,Wa);
    float2 W3 = cmul(W2,Wa);
    float2 W4 = cmul(W3,Wa);
    r[1]=cmul(r[1],Wa);  r[2]=cmul(r[2],W2);
    r[3]=cmul(r[3],W3);  r[4]=cmul(r[4],W4);
    r[5]=cmul(r[5],A5);
    r[6]=cmul(r[6],cmul(A5,Wa));   r[7]=cmul(r[7],cmul(A5,W2));
    r[8]=cmul(r[8],cmul(A5,W3));   r[9]=cmul(r[9],cmul(A5,W4));
    r[10]=cmul(r[10],A10);
    r[11]=cmul(r[11],cmul(A10,Wa)); r[12]=cmul(r[12],cmul(A10,W2));
    r[13]=cmul(r[13],cmul(A10,W3)); r[14]=cmul(r[14],cmul(A10,W4));
    r[15]=cmul(r[15],A15);
    r[16]=cmul(r[16],cmul(A15,Wa)); r[17]=cmul(r[17],cmul(A15,W2));
    r[18]=cmul(r[18],cmul(A15,W3)); r[19]=cmul(r[19],cmul(A15,W4));
}

// ----------------------------- FFT-400 (warp, 20 active lanes): generic -------------
template<bool INV, bool HZ, bool CROP>
__device__ void fft400(float2* __restrict__ lin, float2* __restrict__ tmp, int lane){
    __syncwarp();
    float2 r[20];
    if (lane < 20){
        if (HZ){
            #pragma unroll
            for (int j1=0;j1<5;j1++)  r[j1]=lin[j1*20+lane];
            #pragma unroll
            for (int j1=15;j1<20;j1++) r[j1]=lin[j1*20+lane];
        } else {
            #pragma unroll
            for (int j1=0;j1<20;j1++) r[j1]=lin[j1*20+lane];
        }
        fft20<INV,HZ,false>(r);
        twiddle_apply<INV>(r,lane);
        #pragma unroll
        for (int k1=0;k1<20;k1++) tmp[k1*21+lane]=r[k1];
    }
    __syncwarp();
    if (lane < 20){
        #pragma unroll
        for (int j2=0;j2<20;j2++) r[j2]=tmp[lane*21+j2];
        fft20<INV,false,CROP>(r);
        #pragma unroll
        for (int k2=0;k2<20;k2++)
            if (!CROP || k2<5 || k2>=15) lin[k2*20+lane]=r[k2];
    }
    __syncwarp();
}

// ----------------------------- kB pair-fused: both columns of a warp at once --------
// Corner-compact storage: position p in [0,100) -> p; p in [300,400) -> p-200.
__device__ void fftB_pair(ull* __restrict__ Rc, ull* __restrict__ Ic,
                          ull* __restrict__ tR, ull* __restrict__ tI,
                          int lane, const float2* __restrict__ htA,
                          const float2* __restrict__ htB){
    __syncwarp();
    cp r[20];
    if (lane < 20){
        #pragma unroll
        for (int j1=0;j1<5;j1++){ int p=j1*20+lane; r[j1].R=Rc[p]; r[j1].I=Ic[p]; }
        #pragma unroll
        for (int j1=15;j1<20;j1++){ int p=(j1-15)*20+lane+100; r[j1].R=Rc[p]; r[j1].I=Ic[p]; }
        fft20p<false,true,false>(r);            // fwd stage1 (half-zero)
        twiddle_apply_p<false>(r,lane);
        #pragma unroll
        for (int k1=0;k1<20;k1++){ tR[k1*21+lane]=r[k1].R; tI[k1*21+lane]=r[k1].I; }
    }
    __syncwarp();
    if (lane < 20){
        #pragma unroll
        for (int j2=0;j2<20;j2++){ r[j2].R=tR[lane*21+j2]; r[j2].I=tI[lane*21+j2]; }
    }
    __syncwarp();                               // tmp reads done before overwrite
    if (lane < 20){
        fft20p<false,false,false>(r);           // fwd stage2 -> X at pos 20m+lane
        #pragma unroll
        for (int j1=0;j1<20;j1++){
            float2 hA = htA[j1*20+lane];
            float2 hB = htB[j1*20+lane];
            r[j1] = cpmulw(r[j1], pk2f(hA.x,hB.x), pk2f(hA.y,hB.y));   // *H (pre-scaled)
        }
        fft20p<true,false,false>(r);            // inv stage1
        twiddle_apply_p<true>(r,lane);
        #pragma unroll
        for (int k1=0;k1<20;k1++){ tR[k1*21+lane]=r[k1].R; tI[k1*21+lane]=r[k1].I; }
    }
    __syncwarp();
    if (lane < 20){
        #pragma unroll
        for (int j2=0;j2<20;j2++){ r[j2].R=tR[lane*21+j2]; r[j2].I=tI[lane*21+j2]; }
        fft20p<true,false,true>(r);             // inv stage2, cropped
        #pragma unroll
        for (int k2=0;k2<5;k2++){ int p=k2*20+lane; Rc[p]=r[k2].R; Ic[p]=r[k2].I; }
        #pragma unroll
        for (int k2=15;k2<20;k2++){ int p=(k2-15)*20+lane+100; Rc[p]=r[k2].R; Ic[p]=r[k2].I; }
    }
    __syncwarp();
}

// ----------------------------- kC fused transform: inv FFT -> phasor -> fwd FFT ----
__device__ void fftC_fused(float2* __restrict__ lin, float2* __restrict__ tmp,
                           int lane, const float2* __restrict__ ph){
    __syncwarp();
    float2 r[20];
    if (lane < 20){
        #pragma unroll
        for (int j1=0;j1<20;j1++) r[j1]=lin[j1*20+lane];
        fft20<true,false,false>(r);          // inv stage1
        twiddle_apply<true>(r,lane);
        #pragma unroll
        for (int k1=0;k1<20;k1++) tmp[k1*21+lane]=r[k1];
    }
    __syncwarp();
    if (lane < 20){
        #pragma unroll
        for (int j2=0;j2<20;j2++) r[j2]=tmp[lane*21+j2];
    }
    __syncwarp();                            // tmp reads done before overwrite
    if (lane < 20){
        fft20<true,false,true>(r);           // inv stage2 CROP: corners valid
        if (ph){
            #pragma unroll
            for (int k2=0;k2<5;k2++)   r[k2] = cmul(r[k2], ph[20*k2+lane+100]);
            #pragma unroll
            for (int k2=15;k2<20;k2++) r[k2] = cmul(r[k2], ph[20*k2+lane-300]);
        } else {
            const float sc = 1.f/400.f;
            #pragma unroll
            for (int k2=0;k2<5;k2++){  r[k2].x*=sc; r[k2].y*=sc; }
            #pragma unroll
            for (int k2=15;k2<20;k2++){ r[k2].x*=sc; r[k2].y*=sc; }
        }
        fft20<false,true,false>(r);          // fwd stage1 (half-zero corners)
        twiddle_apply<false>(r,lane);
        #pragma unroll
        for (int k1=0;k1<20;k1++) tmp[k1*21+lane]=r[k1];
    }
    __syncwarp();
    if (lane < 20){
        #pragma unroll
        for (int j2=0;j2<20;j2++) r[j2]=tmp[lane*21+j2];
        fft20<false,false,false>(r);         // fwd stage2
        #pragma unroll
        for (int k2=0;k2<20;k2++) lin[k2*20+lane]=r[k2];
    }
    __syncwarp();
}

#define WPB 4  // warps (transforms) per block for row-FFT kernels

// ----------------------------- init: twiddles + zero histogram -----------------------------
__global__ void kInit(float* out){
    int k = threadIdx.x;
    if (k < 400){
        double ang = -2.0*PI_D*(double)k/400.0;
        g_w400[k] = make_float2((float)cos(ang), (float)sin(ang));
    }
    if (k < 11) out[1250+k] = 0.f;
}

// ----------------------------- precompute layer phasors (pre-scaled by 1/400) ------
__global__ void kPrep(const float* __restrict__ phase){
    int idx = blockIdx.x*256 + threadIdx.x;
    if (idx >= 4*40000) return;
    float p = phase[idx];
    float sv, cv;
    sincospif(2.f*(sinf(p)+1.f), &sv, &cv);   // e^{i*2*pi*(sin(p)+1)}
    const float sc = 1.f/400.f;
    g_PH[idx] = make_float2(cv*sc, sv*sc);
}

// ----------------------------- transpose transfer functions (pre-scaled by 1/400) --
__global__ void kHT(const float2* __restrict__ t0, const float2* __restrict__ t1,
                    const float2* __restrict__ t2){
    __shared__ float2 tile[32][33];
    int m = blockIdx.z;
    const float2* src = (m==0)? t0 : (m==1)? t1 : t2;
    int r0 = blockIdx.y*32, k0 = blockIdx.x*32;
    int tx = threadIdx.x, ty = threadIdx.y;   // 32 x 8
    const float sc = 1.f/400.f;
    for (int yy=ty; yy<32; yy+=8){
        int r = r0+yy, k = k0+tx;
        if (r<400 && k<400) tile[yy][tx] = src[r*400+k];
    }
    __syncthreads();
    for (int yy=ty; yy<32; yy+=8){
        int k = k0+yy, r = r0+tx;
        if (r<400 && k<400){
            float2 v = tile[tx][yy];
            g_HT[(size_t)m*160000 + k*400 + r] = make_float2(v.x*sc, v.y*sc);
        }
    }
}

// ----------------------------- W1 transpose (tiled) + row sums -----------------------------
__global__ void kT(const float* __restrict__ W1){
    __shared__ float tile[32][33];
    int p0 = blockIdx.x*32, h0 = blockIdx.y*32;
    int tx = threadIdx.x, ty = threadIdx.y;   // 32 x 8
    for (int yy=ty; yy<32; yy+=8){
        int hh = h0+yy, p = p0+tx;
        if (hh<512 && p<625) tile[yy][tx] = W1[hh*625+p];
    }
    __syncthreads();
    for (int yy=ty; yy<32; yy+=8){
        int p = p0+yy, hh = h0+tx;
        if (p<625 && hh<512) g_W1T[p*512+hh] = tile[tx][yy];
    }
}
__global__ void kR1(const float* __restrict__ W1){   // grid 512, block 128
    __shared__ float red[128];
    int hh = blockIdx.x, tid = threadIdx.x;
    float s = 0.f;
    for (int p=tid; p<625; p+=128) s += W1[hh*625+p];
    red[tid] = s;
    __syncthreads();
    for (int st=64; st>0; st>>=1){
        if (tid<st) red[tid]+=red[tid+st];
        __syncthreads();
    }
    if (tid==0) g_R1[hh] = red[0];
}

// ----------------------------- A0: real input, 2 rows packed per complex FFT --------
__global__ void kA0(const float* __restrict__ x){   // grid 800, block 128
    __shared__ __align__(16) float2 s_lin[WPB][400];
    __shared__ float2 s_tmp[WPB][421];
    int w = threadIdx.x>>5, lane = threadIdx.x&31;
    int idx = blockIdx.x*WPB + w;                   // 0..3199 row-pairs
    int b = idx/100, pr = idx%100;
    int c0 = 2*pr, c1 = 2*pr+1;
    int i0 = (c0<100)? c0+100 : c0-100;             // logical rows
    int i1 = (c1<100)? c1+100 : c1-100;
    const float4* x0r4 = (const float4*)(x + ((size_t)b*200 + i0)*200);
    const float4* x1r4 = (const float4*)(x + ((size_t)b*200 + i1)*200);
    float2* lin = s_lin[w]; float2* tmp = s_tmp[w];
    if (lane < 25){
        float4 a0 = x0r4[25+lane], b0 = x1r4[25+lane];   // x[100..199] -> lin[0..99]
        lin[4*lane  ] = make_float2(a0.x, b0.x);
        lin[4*lane+1] = make_float2(a0.y, b0.y);
        lin[4*lane+2] = make_float2(a0.z, b0.z);
        lin[4*lane+3] = make_float2(a0.w, b0.w);
        float4 a1 = x0r4[lane],    b1 = x1r4[lane];      // x[0..99] -> lin[300..399]
        lin[300+4*lane  ] = make_float2(a1.x, b1.x);
        lin[300+4*lane+1] = make_float2(a1.y, b1.y);
        lin[300+4*lane+2] = make_float2(a1.z, b1.z);
        lin[300+4*lane+3] = make_float2(a1.w, b1.w);
    }
    fft400<false,true,false>(lin,tmp,lane);
    float2* row0 = g_S + ((size_t)b*200+c0)*400;
    float2* row1 = g_S + ((size_t)b*200+c1)*400;
    for (int k=lane; k<400; k+=32){
        float2 Zk = lin[k];
        float2 Zr = lin[(400-k) & 399];   // (400-k)%400; k=0 -> 0
        row0[k] = make_float2(0.5f*(Zk.x+Zr.x),  0.5f*(Zk.y-Zr.y));
        row1[k] = make_float2(0.5f*(Zk.y+Zr.y), -0.5f*(Zk.x-Zr.x));
    }
}

// ----------------------------- B: pair-fused col FFT*H*IFFT -------------------------
__global__ void __launch_bounds__(128) kB(int hm){
    __shared__ ull Rcol[4][201], Icol[4][201];      // corner-compact SoA
    __shared__ ull tRb[4][421], tIb[4][421];
    int b  = blockIdx.x / 50;
    int k0 = (blockIdx.x % 50) * 8;
    int tid = threadIdx.x;
    const float4* Sb4 = (const float4*)(g_S + (size_t)b*200*400);
    const float2* HT = g_HT + (size_t)hm*160000;

    // stage in: c = compact row index (== compact corner position), q = col-pair
    for (int idx=tid; idx<800; idx+=128){
        int c = idx>>2, q = idx&3;
        float4 v = Sb4[c*200 + (k0>>1) + q];
        Rcol[q][c] = pk2f(v.x, v.z);
        Icol[q][c] = pk2f(v.y, v.w);
    }
    __syncthreads();

    int w = tid>>5, lane = tid&31;
    fftB_pair(Rcol[w], Icol[w], tRb[w], tIb[w], lane,
              HT + (size_t)(k0+2*w  )*400,
              HT + (size_t)(k0+2*w+1)*400);
    __syncthreads();

    // stage out (no scale: folded into HT)
    float4* S2b4 = (float4*)(g_S2 + (size_t)b*200*400);
    for (int idx=tid; idx<800; idx+=128){
        int c = idx>>2, q = idx&3;
        float2 R = U2F(Rcol[q][c]), I = U2F(Icol[q][c]);
        S2b4[c*200 + (k0>>1) + q] = make_float4(R.x, I.x, R.y, I.y);
    }
}

// ----------------------------- C: fused row IFFT -> phasor -> row FFT ---------------
__global__ void kC(int l){   // l < 0: no phasor (first boundary)
    __shared__ __align__(16) float2 s_lin[WPB][400];
    __shared__ float2 s_tmp[WPB][421];
    int w = threadIdx.x>>5, lane = threadIdx.x&31;
    int idx = blockIdx.x*WPB + w;
    int b = idx/200, c = idx%200;
    float2* lin = s_lin[w]; float2* tmp = s_tmp[w];
    const float4* S4 = (const float4*)(g_S2 + ((size_t)b*200+c)*400);
    float4* lin4 = (float4*)lin;
    for (int m4=lane;m4<200;m4+=32) lin4[m4]=S4[m4];
    int i = (c<100)? c+100 : c-100;                 // logical row
    const float2* phrow = (l>=0)? (g_PH + (size_t)l*40000 + i*200) : nullptr;
    fftC_fused(lin,tmp,lane,phrow);
    float4* out4 = (float4*)(g_S + ((size_t)b*200+c)*400);
    const float4* l4 = (const float4*)lin;
    for (int m4=lane;m4<200;m4+=32) out4[m4]=l4[m4];
}

// ----------------------------- CF: row IFFT -> intensity -> horizontal 8-sums ------
__global__ void kCF(){
    __shared__ __align__(16) float2 s_lin[WPB][400];
    __shared__ float2 s_tmp[WPB][421];
    int w = threadIdx.x>>5, lane = threadIdx.x&31;
    int idx = blockIdx.x*WPB + w;
    int b = idx/200, c = idx%200;
    float2* lin = s_lin[w]; float2* tmp = s_tmp[w];
    const float4* S4 = (const float4*)(g_S2 + ((size_t)b*200+c)*400);
    float4* lin4 = (float4*)lin;
    for (int m4=lane;m4<200;m4+=32) lin4[m4]=S4[m4];
    fft400<true,false,true>(lin,tmp,lane);          // cropped inverse
    int i = (c<100)? c+100 : c-100;
    float* pbuf = (float*)tmp;                      // tmp is free now; 200 floats
    const float sc = 1.f/400.f;
    for (int cc=lane;cc<200;cc+=32){
        int rc = (cc<100)? cc : cc+200;
        int j  = (cc<100)? cc+100 : cc-100;
        float vx = lin[rc].x*sc, vy = lin[rc].y*sc;
        pbuf[j] = vx*vx + vy*vy;
    }
    __syncwarp();
    if (lane < 25){
        float s = 0.f;
        #pragma unroll
        for (int v=0; v<8; v++) s += pbuf[lane*8+v];
        g_Pp[((size_t)b*200+i)*25 + lane] = s;
    }
}

// ----------------------------- pooling: vertical sum of 8 partials -> [p][b] -------
__global__ void kPool(){
    int idx = blockIdx.x*256 + threadIdx.x;
    if (idx >= 20000) return;
    int b = idx / 625, p = idx % 625;
    int mi = p/25, mj = p%25;
    const float* base = g_Pp + ((size_t)b*200 + mi*8)*25 + mj;
    float s = 0.f;
    #pragma unroll
    for (int u=0;u<8;u++) s += base[u*25];
    g_pool[p*32+b] = s*(1.f/64.f);
}

// ----------------------------- per-window MLP + voting -----------------------------
#define HSTR 513    // padded hid stride (bank-conflict-free)
__global__ void __launch_bounds__(256) kWin(
                     const float* __restrict__ b1, const float* __restrict__ W2,
                     const float* __restrict__ b2, const float* __restrict__ gamma,
                     const float* __restrict__ beta, float* __restrict__ out)
{
    extern __shared__ float dsm[];
    float* swin = dsm;                    // [cell][b] up to 25*32
    float* hid  = dsm + 800;              // [b][hh] 32*HSTR
    float* lg   = dsm + 800 + 32*HSTR;    // [b][o]  32*10
    __shared__ double red1[256], red2[256];
    __shared__ int   pidx[25];
    __shared__ float s_inv, s_c0;
    __shared__ int   s_a[32];
    __shared__ float s_delta[32];

    int wI = blockIdx.x;
    int i = wI/25, j = wI%25;
    int wr = min(5, 25-i), wc = min(5, 25-j);
    int cells = wr*wc;
    int tid = threadIdx.x;
    if (tid < cells) pidx[tid] = (i + tid/wc)*25 + (j + tid%wc);
    __syncthreads();

    double s1 = 0.0, s2 = 0.0;
    for (int q=tid; q<cells*32; q+=256){
        int cell = q>>5, b = q&31;
        float v = g_pool[pidx[cell]*32 + b];
        swin[q] = v;
        s1 += v; s2 += (double)v*(double)v;
    }
    red1[tid]=s1; red2[tid]=s2;
    __syncthreads();
    for (int st=128; st>0; st>>=1){
        if (tid<st){ red1[tid]+=red1[tid+st]; red2[tid]+=red2[tid+st]; }
        __syncthreads();
    }
    if (tid == 0){
        double mu  = red1[0]/20000.0;
        double var = red2[0]/20000.0 - mu*mu;
        float inv = gamma[0]/(float)sqrt(var + 1e-5);
        s_inv = inv;
        s_c0  = beta[0] - (float)mu*inv;
    }
    __syncthreads();
    float inv = s_inv, c0 = s_c0;

    // hid[b][hh] = relu(c0*R1 + inv*<win,W1win> + b1); 8 batches per thread.
    for (int it=0; it<8; it++){
        int task = it*256 + tid;          // 2048 tasks = 4 bgroups x 512 hh
        int hh = task & 511, bg = task >> 9;
        float acc[8];
        #pragma unroll
        for (int u=0;u<8;u++) acc[u]=0.f;
        for (int cell=0; cell<cells; cell++){
            float wv = g_W1T[pidx[cell]*512+hh];
            const float* sw = swin + cell*32 + bg*8;
            #pragma unroll
            for (int u=0;u<8;u++) acc[u] = fmaf(sw[u], wv, acc[u]);
        }
        float base = fmaf(c0, g_R1[hh], b1[hh]);
        #pragma unroll
        for (int u=0;u<8;u++){
            float pre = fmaf(inv, acc[u], base);
            hid[(bg*8+u)*HSTR + hh] = fmaxf(pre, 0.f);
        }
    }
    __syncthreads();

    for (int t=tid; t<320; t+=256){
        int b = t/10, oo = t%10;
        float acc = b2[oo];
        const float* hb = hid + b*HSTR;
        const float* wv = W2 + oo*512;
        for (int hh=0; hh<512; hh++) acc = fmaf(hb[hh], wv[hh], acc);
        lg[b*10+oo] = acc;
    }
    __syncthreads();

    if (tid < 32){
        int b = tid;
        float lmax = lg[b*10], lmin = lg[b*10];
        int am = 0;
        for (int oo=1;oo<10;oo++){
            float v = lg[b*10+oo];
            if (v > lmax){ lmax = v; am = oo; }
            if (v < lmin)  lmin = v;
        }
        float se = 0.f;
        for (int oo=0;oo<10;oo++) se += expf(lg[b*10+oo]-lmax);
        s_a[b] = am;
        s_delta[b] = (1.f - expf(lmin-lmax))/se;  // pmax - pmin
    }
    __syncthreads();
    if (tid == 0){
        int votes[11];
        for (int k=0;k<11;k++) votes[k]=0;
        for (int b=0;b<32;b++) votes[s_a[b]]++;
        int f0 = 0, best = votes[0];
        for (int k=1;k<11;k++) if (votes[k] > best){ best = votes[k]; f0 = k; }
        float sum = 0.f; int cnt = 0;
        for (int b=0;b<32;b++)
            if (s_a[b]==f0 && s_delta[b]!=0.f){ sum += s_delta[b]; cnt++; }
        int fin;
        if (cnt > 0){ float d1 = sum/(float)cnt; fin = (d1 < 0.2f) ? 0 : f0+1; }
        else fin = f0+1;   // delta1 = NaN; NaN < THR is false
        out[wI]       = (fin==0) ? 0.f : (float)fin;
        out[625+wI]   = (fin!=0) ? 1.f : 0.f;
        atomicAdd(&out[1250+fin], 1.0f);   // exact integer counts -> deterministic
    }
}

// ----------------------------- launch -----------------------------
extern "C" void kernel_launch(void* const* d_in, const int* in_sizes, int n_in,
                              void* d_out, int out_size)
{
    int o = (n_in >= 12 && in_sizes[1] == 1) ? 1 : 0;  // skip batch_size scalar if present
    const float*  x     = (const float*) d_in[0];
    const float2* h     = (const float2*)d_in[1+o];
    const float2* h_pro = (const float2*)d_in[2+o];
    const float2* h_det = (const float2*)d_in[3+o];
    const float*  phase = (const float*) d_in[4+o];
    const float*  W1    = (const float*) d_in[5+o];
    const float*  b1    = (const float*) d_in[6+o];
    const float*  W2    = (const float*) d_in[7+o];
    const float*  b2    = (const float*) d_in[8+o];
    const float*  gamma = (const float*) d_in[9+o];
    const float*  beta  = (const float*) d_in[10+o];
    float* out = (float*)d_out;

    cudaFuncSetAttribute(kWin, cudaFuncAttributeMaxDynamicSharedMemorySize,
                         (800 + 32*HSTR + 320)*4);

    // Order: kB stays the 4th launch (ncu's captured slot) for diagnostics.
    kInit<<<1,512>>>(out);
    kHT <<<dim3(13,13,3),dim3(32,8)>>>(h_pro, h, h_det);   // [0]=h_pro, [1]=h, [2]=h_det
    kA0 <<<800,128>>>(x);                  // 2 rows per FFT (real packing)
    kB  <<<1600,128>>>(0);                 // h_pro  <-- profiled slot
    kPrep<<<625,256>>>(phase);
    kT  <<<dim3(20,16),dim3(32,8)>>>(W1);
    kR1 <<<512,128>>>(W1);
    kC  <<<1600,128>>>(-1);
    for (int l=0; l<4; l++){
        kB <<<1600,128>>>(1);              // h (transposed once, reused 4x)
        kC <<<1600,128>>>(l);
    }
    kB  <<<1600,128>>>(2);                 // h_det
    kCF <<<1600,128>>>();

    kPool<<<79,256>>>();

    kWin<<<625,256,(800 + 32*HSTR + 320)*4>>>(b1, W2, b2, gamma, beta, out);
}